// round 4
// baseline (speedup 1.0000x reference)
#include <cuda_runtime.h>
#include <cuda_bf16.h>
#include <math.h>
#include <stdint.h>

#define SEQ 4096
#define DM  1024
#define TM  128
#define TN  128
#define BK  32

#define NTHREADS 256

// smem buffer layout (per stage): Ahi[128*80B] Alo Bhi Blo
#define A_PITCH  80        // bytes per row (64B data + 16B pad) -> conflict-free ldmatrix
#define AHI_OFF  0
#define ALO_OFF  10240
#define BHI_OFF  20480
#define BLO_OFF  30720
#define BUFB     40960
#define SMEM_BYTES (2 * BUFB)

// ---------------- scratch (device globals; allocation-free) ----------------
__device__ __nv_bfloat16 g_Xhi[SEQ * DM],  g_Xlo[SEQ * DM];
__device__ __nv_bfloat16 g_Qhi[SEQ * DM],  g_Qlo[SEQ * DM];
__device__ __nv_bfloat16 g_Khi[SEQ * DM],  g_Klo[SEQ * DM];
__device__ __nv_bfloat16 g_Vhi[SEQ * DM],  g_Vlo[SEQ * DM];
__device__ __nv_bfloat16 g_Wthi[3 * DM * DM], g_Wtlo[3 * DM * DM]; // W^T [n][k]
__device__ __nv_bfloat16 g_Phi[(size_t)SEQ * SEQ], g_Plo[(size_t)SEQ * SEQ];
__device__ float         g_S  [(size_t)SEQ * SEQ];

// ---------------- PTX helpers (baseline PTX only; no arch-'a' features) ----
__device__ __forceinline__ uint32_t smem_u32(const void* p) {
    uint32_t a;
    asm("{ .reg .u64 t; cvta.to.shared.u64 t, %1; cvt.u32.u64 %0, t; }" : "=r"(a) : "l"(p));
    return a;
}

#define CP16(dst, src) \
    asm volatile("cp.async.cg.shared.global [%0], [%1], 16;" :: "r"(dst), "l"(src) : "memory")
#define CP_COMMIT() asm volatile("cp.async.commit_group;" ::: "memory")
#define CP_WAIT(n)  asm volatile("cp.async.wait_group %0;" :: "n"(n) : "memory")

#define LDSM_X4(r, addr) \
    asm volatile("ldmatrix.sync.aligned.m8n8.x4.shared.b16 {%0,%1,%2,%3}, [%4];" \
        : "=r"((r)[0]), "=r"((r)[1]), "=r"((r)[2]), "=r"((r)[3]) : "r"(addr))
#define LDSM_X2(r, addr) \
    asm volatile("ldmatrix.sync.aligned.m8n8.x2.shared.b16 {%0,%1}, [%2];" \
        : "=r"((r)[0]), "=r"((r)[1]) : "r"(addr))
#define LDSM_X2T(r, addr) \
    asm volatile("ldmatrix.sync.aligned.m8n8.x2.trans.shared.b16 {%0,%1}, [%2];" \
        : "=r"((r)[0]), "=r"((r)[1]) : "r"(addr))

#define MMA_BF16(d, a, b) \
    asm volatile("mma.sync.aligned.m16n8k16.row.col.f32.bf16.bf16.f32 " \
        "{%0,%1,%2,%3}, {%4,%5,%6,%7}, {%8,%9}, {%0,%1,%2,%3};" \
        : "+f"((d)[0]), "+f"((d)[1]), "+f"((d)[2]), "+f"((d)[3]) \
        : "r"((a)[0]), "r"((a)[1]), "r"((a)[2]), "r"((a)[3]), "r"((b)[0]), "r"((b)[1]))

// ---------------- split helpers ----------------
__device__ __forceinline__ void split1(float v, __nv_bfloat16& h, __nv_bfloat16& l) {
    h = __float2bfloat16(v);
    l = __float2bfloat16(v - __bfloat162float(h));
}
__device__ __forceinline__ void split2(float x, float y, uint32_t& hu, uint32_t& lu) {
    __nv_bfloat162 h, l;
    h.x = __float2bfloat16(x);
    h.y = __float2bfloat16(y);
    l.x = __float2bfloat16(x - __bfloat162float(h.x));
    l.y = __float2bfloat16(y - __bfloat162float(h.y));
    hu = *reinterpret_cast<uint32_t*>(&h);
    lu = *reinterpret_cast<uint32_t*>(&l);
}

// ---------------------------------------------------------------------------
// X split: fp32 -> hi/lo bf16
// ---------------------------------------------------------------------------
__global__ __launch_bounds__(256) void xsplit_kernel(const float* __restrict__ x)
{
    int i = (blockIdx.x * 256 + threadIdx.x) * 4;
    float4 v = *(const float4*)(x + i);
    uint32_t h0, l0, h1, l1;
    split2(v.x, v.y, h0, l0);
    split2(v.z, v.w, h1, l1);
    *(uint2*)(g_Xhi + i) = make_uint2(h0, h1);
    *(uint2*)(g_Xlo + i) = make_uint2(l0, l1);
}

// ---------------------------------------------------------------------------
// W transpose + split: W [k][n] fp32 -> Wt hi/lo [n][k] bf16
// ---------------------------------------------------------------------------
__global__ __launch_bounds__(256) void wtrans_kernel(
    const float* __restrict__ Wq, const float* __restrict__ Wk, const float* __restrict__ Wv)
{
    __shared__ float t[32][33];
    const float* W = (blockIdx.z == 0) ? Wq : (blockIdx.z == 1) ? Wk : Wv;
    const size_t zoff = (size_t)blockIdx.z * DM * DM;
    const int n0 = blockIdx.x * 32, k0 = blockIdx.y * 32;
    const int tx = threadIdx.x, ty = threadIdx.y;  // (32, 8)

#pragma unroll
    for (int j = 0; j < 32; j += 8)
        t[ty + j][tx] = W[(size_t)(k0 + ty + j) * DM + n0 + tx];
    __syncthreads();
#pragma unroll
    for (int j = 0; j < 32; j += 8) {
        float v = t[tx][ty + j];
        __nv_bfloat16 h, l; split1(v, h, l);
        size_t o = zoff + (size_t)(n0 + ty + j) * DM + k0 + tx;
        g_Wthi[o] = h; g_Wtlo[o] = l;
    }
}

// ---------------------------------------------------------------------------
// Unified split-bf16 mma.sync GEMM. 128x128 CTA tile, 8 warps of 32x64, BK=32,
// cp.async double-buffered.
//  MODE 0: proj  (z: 0=Q,1=K,2=V). A=Xhi/lo, B=Wt[z]. out split bf16.
//  MODE 3: scores. A=Qhi/lo, B=Khi/lo. tri grid; out g_S fp32 (scaled+masked).
//  MODE 4: PV. A=Phi/lo, B=Vhi/lo stored [k][n] (trans ldmatrix). out fp32.
// ---------------------------------------------------------------------------
template<int MODE>
__global__ __launch_bounds__(NTHREADS, 1) void hgemm(float* __restrict__ Oext)
{
    extern __shared__ char smem[];
    const uint32_t sb = smem_u32(smem);
    const int tid  = threadIdx.x;
    const int wid  = tid >> 5;
    const int lane = tid & 31;
    const int wr   = wid & 3;        // warp row (32 rows)
    const int wc   = wid >> 2;       // warp col (64 cols)

    int m0, n0, br = 0, bc = 0;
    if (MODE == 3) {
        int i = (int)blockIdx.x;
        br = (int)((sqrtf(8.0f * (float)i + 1.0f) - 1.0f) * 0.5f);
        while ((br + 1) * (br + 2) / 2 <= i) br++;
        while (br * (br + 1) / 2 > i)        br--;
        bc = i - br * (br + 1) / 2;
        m0 = br * TM; n0 = bc * TN;
    } else {
        m0 = blockIdx.y * TM; n0 = blockIdx.x * TN;
    }

    const __nv_bfloat16 *Ah, *Al, *Bh, *Bl;
    int lda, ldb, Kext;
    if (MODE == 0) {
        Ah = g_Xhi; Al = g_Xlo; lda = DM; Kext = DM; ldb = DM;
        Bh = g_Wthi + (size_t)blockIdx.z * DM * DM;
        Bl = g_Wtlo + (size_t)blockIdx.z * DM * DM;
    } else if (MODE == 3) {
        Ah = g_Qhi; Al = g_Qlo; lda = DM; Kext = DM; ldb = DM;
        Bh = g_Khi; Bl = g_Klo;
    } else {
        Ah = g_Phi; Al = g_Plo; lda = SEQ; Kext = m0 + TM; ldb = DM;
        Bh = g_Vhi; Bl = g_Vlo;   // [k][n], n contiguous
    }

    float acc[2][8][4];
#pragma unroll
    for (int mi = 0; mi < 2; mi++)
#pragma unroll
        for (int nf = 0; nf < 8; nf++)
#pragma unroll
            for (int q = 0; q < 4; q++) acc[mi][nf][q] = 0.0f;

    const int nch = Kext / BK;

    // ---- chunk loader
    auto load_chunk = [&](int c) {
        const int k0  = c * BK;
        const uint32_t base = sb + (uint32_t)(c & 1) * BUFB;
        if (MODE == 4) {
            // A: 128 rows x 32 k (4 chunks of 16B)
            for (int u = tid; u < 512; u += NTHREADS) {
                int row = u >> 2, ch = u & 3;
                size_t go = (size_t)(m0 + row) * lda + k0 + ch * 8;
                uint32_t da = base + AHI_OFF + row * A_PITCH + ch * 16;
                CP16(da,         Ah + go);
                CP16(da + ALO_OFF, Al + go);
            }
            // B: 32 k-rows x 128 n, XOR-swizzled chunks
            for (int u = tid; u < 512; u += NTHREADS) {
                int k = u >> 4, ch = u & 15;
                size_t go = (size_t)(k0 + k) * ldb + n0 + ch * 8;
                uint32_t db = base + BHI_OFF + k * 256 + ((ch ^ (k & 7)) << 4);
                CP16(db,             Bh + go);
                CP16(db + (BLO_OFF - BHI_OFF), Bl + go);
            }
        } else {
            for (int u = tid; u < 512; u += NTHREADS) {
                int row = u >> 2, ch = u & 3;
                size_t ga = (size_t)(m0 + row) * lda + k0 + ch * 8;
                size_t gb = (size_t)(n0 + row) * ldb + k0 + ch * 8;
                uint32_t da = base + AHI_OFF + row * A_PITCH + ch * 16;
                uint32_t db = base + BHI_OFF + row * A_PITCH + ch * 16;
                CP16(da,           Ah + ga);
                CP16(da + ALO_OFF, Al + ga);
                CP16(db,           Bh + gb);
                CP16(db + (BLO_OFF - BHI_OFF), Bl + gb);
            }
        }
    };

    load_chunk(0);
    CP_COMMIT();

    for (int c = 0; c < nch; c++) {
        if (c + 1 < nch) { load_chunk(c + 1); CP_COMMIT(); CP_WAIT(1); }
        else             { CP_WAIT(0); }
        __syncthreads();

        const uint32_t base = sb + (uint32_t)(c & 1) * BUFB;
#pragma unroll
        for (int ks = 0; ks < 2; ks++) {
            uint32_t ah[2][4], al[2][4];
#pragma unroll
            for (int mi = 0; mi < 2; mi++) {
                uint32_t aaddr = base + AHI_OFF
                    + (wr * 32 + mi * 16 + (lane & 15)) * A_PITCH
                    + (ks * 2 + (lane >> 4)) * 16;
                LDSM_X4(ah[mi], aaddr);
                LDSM_X4(al[mi], aaddr + ALO_OFF);
            }
#pragma unroll
            for (int nf = 0; nf < 8; nf++) {
                uint32_t bh[2], bl[2];
                if (MODE == 4) {
                    int klo = ks * 16 + (lane & 15);
                    uint32_t baddr = base + BHI_OFF + klo * 256
                        + (((wc * 8 + nf) ^ (klo & 7)) << 4);
                    LDSM_X2T(bh, baddr);
                    LDSM_X2T(bl, baddr + (BLO_OFF - BHI_OFF));
                } else {
                    uint32_t baddr = base + BHI_OFF
                        + (wc * 64 + nf * 8 + (lane & 7)) * A_PITCH
                        + (ks * 2 + ((lane >> 3) & 1)) * 16;
                    LDSM_X2(bh, baddr);
                    LDSM_X2(bl, baddr + (BLO_OFF - BHI_OFF));
                }
#pragma unroll
                for (int mi = 0; mi < 2; mi++) {
                    MMA_BF16(acc[mi][nf], ah[mi], bh);
                    MMA_BF16(acc[mi][nf], ah[mi], bl);
                    MMA_BF16(acc[mi][nf], al[mi], bh);
                }
            }
        }
        __syncthreads();
    }

    // ---- epilogue
    const int rb = m0 + wr * 32 + (lane >> 2);
    const int cb = n0 + wc * 64 + 2 * (lane & 3);
    const float scale = 0.03125f;   // 1/sqrt(1024), MODE 3 only

#pragma unroll
    for (int mi = 0; mi < 2; mi++) {
#pragma unroll
        for (int nf = 0; nf < 8; nf++) {
            int r0 = rb + mi * 16;
            int cc = cb + nf * 8;
            float v00 = acc[mi][nf][0], v01 = acc[mi][nf][1];
            float v10 = acc[mi][nf][2], v11 = acc[mi][nf][3];
            if (MODE == 0) {
                __nv_bfloat16* Oh = (blockIdx.z == 0) ? g_Qhi : (blockIdx.z == 1) ? g_Khi : g_Vhi;
                __nv_bfloat16* Ol = (blockIdx.z == 0) ? g_Qlo : (blockIdx.z == 1) ? g_Klo : g_Vlo;
                uint32_t h, l;
                split2(v00, v01, h, l);
                *(uint32_t*)(Oh + (size_t)r0 * DM + cc) = h;
                *(uint32_t*)(Ol + (size_t)r0 * DM + cc) = l;
                split2(v10, v11, h, l);
                *(uint32_t*)(Oh + (size_t)(r0 + 8) * DM + cc) = h;
                *(uint32_t*)(Ol + (size_t)(r0 + 8) * DM + cc) = l;
            } else if (MODE == 3) {
                if (br == bc) {
                    float* s0 = g_S + (size_t)r0 * SEQ + cc;
                    s0[0] = (cc + 0 <= r0) ? v00 * scale : -INFINITY;
                    s0[1] = (cc + 1 <= r0) ? v01 * scale : -INFINITY;
                    float* s1 = g_S + (size_t)(r0 + 8) * SEQ + cc;
                    s1[0] = (cc + 0 <= r0 + 8) ? v10 * scale : -INFINITY;
                    s1[1] = (cc + 1 <= r0 + 8) ? v11 * scale : -INFINITY;
                } else {
                    *(float2*)(g_S + (size_t)r0 * SEQ + cc)       = make_float2(v00 * scale, v01 * scale);
                    *(float2*)(g_S + (size_t)(r0 + 8) * SEQ + cc) = make_float2(v10 * scale, v11 * scale);
                }
            } else {
                *(float2*)(Oext + (size_t)r0 * DM + cc)       = make_float2(v00, v01);
                *(float2*)(Oext + (size_t)(r0 + 8) * DM + cc) = make_float2(v10, v11);
            }
        }
    }
}

// ---------------------------------------------------------------------------
// Row softmax over g_S; emits P hi/lo bf16. Row r covers [0, roundup128(r+1)).
// ---------------------------------------------------------------------------
__global__ __launch_bounds__(256) void softmax_kernel()
{
    const int r   = (int)blockIdx.x;
    const int L   = (((r >> 7) + 1) << 7);
    const float* row = g_S + (size_t)r * SEQ;
    const int tid = threadIdx.x;
    __shared__ float red[256];

    float v[16];
    int   cnt = 0;
    float mx  = -INFINITY;
    for (int c = tid; c < L; c += 256) {
        float t = row[c];
        v[cnt++] = t;
        mx = fmaxf(mx, t);
    }
    red[tid] = mx;
    __syncthreads();
#pragma unroll
    for (int s = 128; s > 0; s >>= 1) {
        if (tid < s) red[tid] = fmaxf(red[tid], red[tid + s]);
        __syncthreads();
    }
    mx = red[0];
    __syncthreads();

    float sum = 0.0f;
    for (int j = 0; j < cnt; j++) {
        v[j] = expf(v[j] - mx);
        sum += v[j];
    }
    red[tid] = sum;
    __syncthreads();
#pragma unroll
    for (int s = 128; s > 0; s >>= 1) {
        if (tid < s) red[tid] += red[tid + s];
        __syncthreads();
    }
    const float rinv = 1.0f / red[0];

    cnt = 0;
    for (int c = tid; c < L; c += 256) {
        float p = v[cnt++] * rinv;
        __nv_bfloat16 h, l; split1(p, h, l);
        g_Phi[(size_t)r * SEQ + c] = h;
        g_Plo[(size_t)r * SEQ + c] = l;
    }
}

// ---------------------------------------------------------------------------
extern "C" void kernel_launch(void* const* d_in, const int* in_sizes, int n_in,
                              void* d_out, int out_size)
{
    const float* x  = (const float*)d_in[0];
    const float* Wq = (const float*)d_in[1];
    const float* Wk = (const float*)d_in[2];
    const float* Wv = (const float*)d_in[3];
    float* out = (float*)d_out;
    (void)in_sizes; (void)n_in; (void)out_size;

    cudaFuncSetAttribute(hgemm<0>, cudaFuncAttributeMaxDynamicSharedMemorySize, SMEM_BYTES);
    cudaFuncSetAttribute(hgemm<3>, cudaFuncAttributeMaxDynamicSharedMemorySize, SMEM_BYTES);
    cudaFuncSetAttribute(hgemm<4>, cudaFuncAttributeMaxDynamicSharedMemorySize, SMEM_BYTES);

    // 0) operand prep
    xsplit_kernel<<<SEQ * DM / (256 * 4), 256>>>(x);
    wtrans_kernel<<<dim3(DM / 32, DM / 32, 3), dim3(32, 8)>>>(Wq, Wk, Wv);

    // 1) projections Q/K/V (z selects weight + destination)
    hgemm<0><<<dim3(DM / TN, SEQ / TM, 3), NTHREADS, SMEM_BYTES>>>(nullptr);

    // 2) causal scores (lower-triangular blocks only)
    const int nTri = (SEQ / TM) * (SEQ / TM + 1) / 2;   // 528
    hgemm<3><<<nTri, NTHREADS, SMEM_BYTES>>>(nullptr);

    // 3) softmax -> P hi/lo
    softmax_kernel<<<SEQ, 256>>>();

    // 4) O = P @ V
    hgemm<4><<<dim3(DM / TN, SEQ / TM), NTHREADS, SMEM_BYTES>>>(out);
}

// round 6
// speedup vs baseline: 1.1717x; 1.1717x over previous
#include <cuda_runtime.h>
#include <cuda_bf16.h>
#include <math.h>
#include <stdint.h>

#define SEQ 4096
#define DM  1024
#define TM  128
#define TN  128
#define BK  32

#define NTHREADS 256

// smem buffer layout (per stage): Ahi[128*80B] Alo Bhi Blo
#define A_PITCH  80        // bytes per row (64B data + 16B pad) -> conflict-free ldmatrix
#define AHI_OFF  0
#define ALO_OFF  10240
#define BHI_OFF  20480
#define BLO_OFF  30720
#define BUFB     40960
#define SMEM_BYTES (2 * BUFB)

// ---------------- scratch (device globals; allocation-free) ----------------
__device__ __nv_bfloat16 g_Xhi[SEQ * DM],  g_Xlo[SEQ * DM];
__device__ __nv_bfloat16 g_Qhi[SEQ * DM],  g_Qlo[SEQ * DM];
__device__ __nv_bfloat16 g_Khi[SEQ * DM],  g_Klo[SEQ * DM];
__device__ __nv_bfloat16 g_Vhi[SEQ * DM],  g_Vlo[SEQ * DM];
__device__ __nv_bfloat16 g_Wthi[3 * DM * DM], g_Wtlo[3 * DM * DM]; // W^T [n][k]
__device__ __nv_bfloat16 g_Phi[(size_t)SEQ * SEQ], g_Plo[(size_t)SEQ * SEQ];
__device__ float         g_S  [(size_t)SEQ * SEQ];

// ---------------- PTX helpers (baseline PTX only; no arch-'a' features) ----
__device__ __forceinline__ uint32_t smem_u32(const void* p) {
    uint32_t a;
    asm("{ .reg .u64 t; cvta.to.shared.u64 t, %1; cvt.u32.u64 %0, t; }" : "=r"(a) : "l"(p));
    return a;
}

#define CP16(dst, src) \
    asm volatile("cp.async.cg.shared.global [%0], [%1], 16;" :: "r"(dst), "l"(src) : "memory")
#define CP_COMMIT() asm volatile("cp.async.commit_group;" ::: "memory")
#define CP_WAIT(n)  asm volatile("cp.async.wait_group %0;" :: "n"(n) : "memory")

#define LDSM_X4(r, addr) \
    asm volatile("ldmatrix.sync.aligned.m8n8.x4.shared.b16 {%0,%1,%2,%3}, [%4];" \
        : "=r"((r)[0]), "=r"((r)[1]), "=r"((r)[2]), "=r"((r)[3]) : "r"(addr))
#define LDSM_X4T(r, addr) \
    asm volatile("ldmatrix.sync.aligned.m8n8.x4.trans.shared.b16 {%0,%1,%2,%3}, [%4];" \
        : "=r"((r)[0]), "=r"((r)[1]), "=r"((r)[2]), "=r"((r)[3]) : "r"(addr))

#define MMA_BF16(d, a, b0, b1) \
    asm volatile("mma.sync.aligned.m16n8k16.row.col.f32.bf16.bf16.f32 " \
        "{%0,%1,%2,%3}, {%4,%5,%6,%7}, {%8,%9}, {%0,%1,%2,%3};" \
        : "+f"((d)[0]), "+f"((d)[1]), "+f"((d)[2]), "+f"((d)[3]) \
        : "r"((a)[0]), "r"((a)[1]), "r"((a)[2]), "r"((a)[3]), "r"(b0), "r"(b1))

// ---------------- split helpers ----------------
__device__ __forceinline__ void split1(float v, __nv_bfloat16& h, __nv_bfloat16& l) {
    h = __float2bfloat16(v);
    l = __float2bfloat16(v - __bfloat162float(h));
}
__device__ __forceinline__ void split2(float x, float y, uint32_t& hu, uint32_t& lu) {
    __nv_bfloat162 h, l;
    h.x = __float2bfloat16(x);
    h.y = __float2bfloat16(y);
    l.x = __float2bfloat16(x - __bfloat162float(h.x));
    l.y = __float2bfloat16(y - __bfloat162float(h.y));
    hu = *reinterpret_cast<uint32_t*>(&h);
    lu = *reinterpret_cast<uint32_t*>(&l);
}

// ---------------------------------------------------------------------------
// X split: fp32 -> hi/lo bf16
// ---------------------------------------------------------------------------
__global__ __launch_bounds__(256) void xsplit_kernel(const float* __restrict__ x)
{
    int i = (blockIdx.x * 256 + threadIdx.x) * 4;
    float4 v = *(const float4*)(x + i);
    uint32_t h0, l0, h1, l1;
    split2(v.x, v.y, h0, l0);
    split2(v.z, v.w, h1, l1);
    *(uint2*)(g_Xhi + i) = make_uint2(h0, h1);
    *(uint2*)(g_Xlo + i) = make_uint2(l0, l1);
}

// ---------------------------------------------------------------------------
// W transpose + split: W [k][n] fp32 -> Wt hi/lo [n][k] bf16
// ---------------------------------------------------------------------------
__global__ __launch_bounds__(256) void wtrans_kernel(
    const float* __restrict__ Wq, const float* __restrict__ Wk, const float* __restrict__ Wv)
{
    __shared__ float t[32][33];
    const float* W = (blockIdx.z == 0) ? Wq : (blockIdx.z == 1) ? Wk : Wv;
    const size_t zoff = (size_t)blockIdx.z * DM * DM;
    const int n0 = blockIdx.x * 32, k0 = blockIdx.y * 32;
    const int tx = threadIdx.x, ty = threadIdx.y;  // (32, 8)

#pragma unroll
    for (int j = 0; j < 32; j += 8)
        t[ty + j][tx] = W[(size_t)(k0 + ty + j) * DM + n0 + tx];
    __syncthreads();
#pragma unroll
    for (int j = 0; j < 32; j += 8) {
        float v = t[tx][ty + j];
        __nv_bfloat16 h, l; split1(v, h, l);
        size_t o = zoff + (size_t)(n0 + ty + j) * DM + k0 + tx;
        g_Wthi[o] = h; g_Wtlo[o] = l;
    }
}

// ---------------------------------------------------------------------------
// Unified split-bf16 mma.sync GEMM. 128x128 CTA tile, 8 warps of 32x64, BK=32,
// cp.async double-buffered, 2 CTAs/SM (128-reg cap).
//  MODE 0: proj  (z: 0=Q,1=K,2=V). A=Xhi/lo, B=Wt[z]. out split bf16.
//  MODE 3: scores. A=Qhi/lo, B=Khi/lo. tri grid; out g_S fp32 (scaled+masked).
//  MODE 4: PV. A=Phi/lo, B=Vhi/lo stored [k][n] (trans ldmatrix). out fp32.
// ---------------------------------------------------------------------------
template<int MODE>
__global__ __launch_bounds__(NTHREADS, 2) void hgemm(float* __restrict__ Oext)
{
    extern __shared__ char smem[];
    const uint32_t sb = smem_u32(smem);
    const int tid  = threadIdx.x;
    const int wid  = tid >> 5;
    const int lane = tid & 31;
    const int wr   = wid & 3;        // warp row (32 rows)
    const int wc   = wid >> 2;       // warp col (64 cols)

    int m0, n0, br = 0, bc = 0;
    if (MODE == 3) {
        int i = (int)blockIdx.x;
        br = (int)((sqrtf(8.0f * (float)i + 1.0f) - 1.0f) * 0.5f);
        while ((br + 1) * (br + 2) / 2 <= i) br++;
        while (br * (br + 1) / 2 > i)        br--;
        bc = i - br * (br + 1) / 2;
        m0 = br * TM; n0 = bc * TN;
    } else {
        m0 = blockIdx.y * TM; n0 = blockIdx.x * TN;
    }

    const __nv_bfloat16 *Ah, *Al, *Bh, *Bl;
    int lda, ldb, Kext;
    if (MODE == 0) {
        Ah = g_Xhi; Al = g_Xlo; lda = DM; Kext = DM; ldb = DM;
        Bh = g_Wthi + (size_t)blockIdx.z * DM * DM;
        Bl = g_Wtlo + (size_t)blockIdx.z * DM * DM;
    } else if (MODE == 3) {
        Ah = g_Qhi; Al = g_Qlo; lda = DM; Kext = DM; ldb = DM;
        Bh = g_Khi; Bl = g_Klo;
    } else {
        Ah = g_Phi; Al = g_Plo; lda = SEQ; Kext = m0 + TM; ldb = DM;
        Bh = g_Vhi; Bl = g_Vlo;   // [k][n], n contiguous
    }

    float acc[2][8][4];
#pragma unroll
    for (int mi = 0; mi < 2; mi++)
#pragma unroll
        for (int nf = 0; nf < 8; nf++)
#pragma unroll
            for (int q = 0; q < 4; q++) acc[mi][nf][q] = 0.0f;

    const int nch = Kext / BK;

    // ---- chunk loader
    auto load_chunk = [&](int c) {
        const int k0  = c * BK;
        const uint32_t base = sb + (uint32_t)(c & 1) * BUFB;
        if (MODE == 4) {
            // A: 128 rows x 32 k (4 chunks of 16B)
            for (int u = tid; u < 512; u += NTHREADS) {
                int row = u >> 2, ch = u & 3;
                size_t go = (size_t)(m0 + row) * lda + k0 + ch * 8;
                uint32_t da = base + AHI_OFF + row * A_PITCH + ch * 16;
                CP16(da,           Ah + go);
                CP16(da + ALO_OFF, Al + go);
            }
            // B: 32 k-rows x 128 n, XOR-swizzled chunks
            for (int u = tid; u < 512; u += NTHREADS) {
                int k = u >> 4, ch = u & 15;
                size_t go = (size_t)(k0 + k) * ldb + n0 + ch * 8;
                uint32_t db = base + BHI_OFF + k * 256 + ((ch ^ (k & 7)) << 4);
                CP16(db,                       Bh + go);
                CP16(db + (BLO_OFF - BHI_OFF), Bl + go);
            }
        } else {
            for (int u = tid; u < 512; u += NTHREADS) {
                int row = u >> 2, ch = u & 3;
                size_t ga = (size_t)(m0 + row) * lda + k0 + ch * 8;
                size_t gb = (size_t)(n0 + row) * ldb + k0 + ch * 8;
                uint32_t da = base + AHI_OFF + row * A_PITCH + ch * 16;
                uint32_t db = base + BHI_OFF + row * A_PITCH + ch * 16;
                CP16(da,           Ah + ga);
                CP16(da + ALO_OFF, Al + ga);
                CP16(db,           Bh + gb);
                CP16(db + (BLO_OFF - BHI_OFF), Bl + gb);
            }
        }
    };

    load_chunk(0);
    CP_COMMIT();

    for (int c = 0; c < nch; c++) {
        if (c + 1 < nch) { load_chunk(c + 1); CP_COMMIT(); CP_WAIT(1); }
        else             { CP_WAIT(0); }
        __syncthreads();

        const uint32_t base = sb + (uint32_t)(c & 1) * BUFB;
#pragma unroll
        for (int ks = 0; ks < 2; ks++) {
            uint32_t ah[2][4], al[2][4];
#pragma unroll
            for (int mi = 0; mi < 2; mi++) {
                uint32_t aaddr = base + AHI_OFF
                    + (wr * 32 + mi * 16 + (lane & 15)) * A_PITCH
                    + (ks * 2 + (lane >> 4)) * 16;
                LDSM_X4(ah[mi], aaddr);
                LDSM_X4(al[mi], aaddr + ALO_OFF);
            }
            // B fragments: two n-tiles per ldmatrix.x4
#pragma unroll
            for (int nfp = 0; nfp < 4; nfp++) {
                uint32_t bh[4], bl[4];
                if (MODE == 4) {
                    int klo    = ks * 16 + (lane & 15);
                    int cchunk = wc * 8 + nfp * 2 + ((lane >> 4) & 1);
                    uint32_t baddr = base + BHI_OFF + klo * 256
                        + ((cchunk ^ (klo & 7)) << 4);
                    LDSM_X4T(bh, baddr);
                    LDSM_X4T(bl, baddr + (BLO_OFF - BHI_OFF));
                } else {
                    uint32_t baddr = base + BHI_OFF
                        + (wc * 64 + nfp * 16 + (lane & 7) + ((lane >> 4) & 1) * 8) * A_PITCH
                        + ks * 32 + ((lane >> 3) & 1) * 16;
                    LDSM_X4(bh, baddr);
                    LDSM_X4(bl, baddr + (BLO_OFF - BHI_OFF));
                }
#pragma unroll
                for (int mi = 0; mi < 2; mi++) {
                    MMA_BF16(acc[mi][nfp * 2],     ah[mi], bh[0], bh[1]);
                    MMA_BF16(acc[mi][nfp * 2],     ah[mi], bl[0], bl[1]);
                    MMA_BF16(acc[mi][nfp * 2],     al[mi], bh[0], bh[1]);
                    MMA_BF16(acc[mi][nfp * 2 + 1], ah[mi], bh[2], bh[3]);
                    MMA_BF16(acc[mi][nfp * 2 + 1], ah[mi], bl[2], bl[3]);
                    MMA_BF16(acc[mi][nfp * 2 + 1], al[mi], bh[2], bh[3]);
                }
            }
        }
        __syncthreads();
    }

    // ---- epilogue
    const int rb = m0 + wr * 32 + (lane >> 2);
    const int cb = n0 + wc * 64 + 2 * (lane & 3);
    const float scale = 0.03125f;   // 1/sqrt(1024), MODE 3 only

#pragma unroll
    for (int mi = 0; mi < 2; mi++) {
#pragma unroll
        for (int nf = 0; nf < 8; nf++) {
            int r0 = rb + mi * 16;
            int cc = cb + nf * 8;
            float v00 = acc[mi][nf][0], v01 = acc[mi][nf][1];
            float v10 = acc[mi][nf][2], v11 = acc[mi][nf][3];
            if (MODE == 0) {
                __nv_bfloat16* Oh = (blockIdx.z == 0) ? g_Qhi : (blockIdx.z == 1) ? g_Khi : g_Vhi;
                __nv_bfloat16* Ol = (blockIdx.z == 0) ? g_Qlo : (blockIdx.z == 1) ? g_Klo : g_Vlo;
                uint32_t h, l;
                split2(v00, v01, h, l);
                *(uint32_t*)(Oh + (size_t)r0 * DM + cc) = h;
                *(uint32_t*)(Ol + (size_t)r0 * DM + cc) = l;
                split2(v10, v11, h, l);
                *(uint32_t*)(Oh + (size_t)(r0 + 8) * DM + cc) = h;
                *(uint32_t*)(Ol + (size_t)(r0 + 8) * DM + cc) = l;
            } else if (MODE == 3) {
                if (br == bc) {
                    float* s0 = g_S + (size_t)r0 * SEQ + cc;
                    s0[0] = (cc + 0 <= r0) ? v00 * scale : -INFINITY;
                    s0[1] = (cc + 1 <= r0) ? v01 * scale : -INFINITY;
                    float* s1 = g_S + (size_t)(r0 + 8) * SEQ + cc;
                    s1[0] = (cc + 0 <= r0 + 8) ? v10 * scale : -INFINITY;
                    s1[1] = (cc + 1 <= r0 + 8) ? v11 * scale : -INFINITY;
                } else {
                    *(float2*)(g_S + (size_t)r0 * SEQ + cc)       = make_float2(v00 * scale, v01 * scale);
                    *(float2*)(g_S + (size_t)(r0 + 8) * SEQ + cc) = make_float2(v10 * scale, v11 * scale);
                }
            } else {
                *(float2*)(Oext + (size_t)r0 * DM + cc)       = make_float2(v00, v01);
                *(float2*)(Oext + (size_t)(r0 + 8) * DM + cc) = make_float2(v10, v11);
            }
        }
    }
}

// ---------------------------------------------------------------------------
// Row softmax over g_S; emits P hi/lo bf16. Row r covers [0, roundup128(r+1)).
// ---------------------------------------------------------------------------
__global__ __launch_bounds__(256) void softmax_kernel()
{
    const int r   = (int)blockIdx.x;
    const int L   = (((r >> 7) + 1) << 7);
    const float* row = g_S + (size_t)r * SEQ;
    const int tid = threadIdx.x;
    __shared__ float red[256];

    float v[16];
    int   cnt = 0;
    float mx  = -INFINITY;
    for (int c = tid; c < L; c += 256) {
        float t = row[c];
        v[cnt++] = t;
        mx = fmaxf(mx, t);
    }
    red[tid] = mx;
    __syncthreads();
#pragma unroll
    for (int s = 128; s > 0; s >>= 1) {
        if (tid < s) red[tid] = fmaxf(red[tid], red[tid + s]);
        __syncthreads();
    }
    mx = red[0];
    __syncthreads();

    float sum = 0.0f;
    for (int j = 0; j < cnt; j++) {
        v[j] = expf(v[j] - mx);
        sum += v[j];
    }
    red[tid] = sum;
    __syncthreads();
#pragma unroll
    for (int s = 128; s > 0; s >>= 1) {
        if (tid < s) red[tid] += red[tid + s];
        __syncthreads();
    }
    const float rinv = 1.0f / red[0];

    cnt = 0;
    for (int c = tid; c < L; c += 256) {
        float p = v[cnt++] * rinv;
        __nv_bfloat16 h, l; split1(p, h, l);
        g_Phi[(size_t)r * SEQ + c] = h;
        g_Plo[(size_t)r * SEQ + c] = l;
    }
}

// ---------------------------------------------------------------------------
extern "C" void kernel_launch(void* const* d_in, const int* in_sizes, int n_in,
                              void* d_out, int out_size)
{
    const float* x  = (const float*)d_in[0];
    const float* Wq = (const float*)d_in[1];
    const float* Wk = (const float*)d_in[2];
    const float* Wv = (const float*)d_in[3];
    float* out = (float*)d_out;
    (void)in_sizes; (void)n_in; (void)out_size;

    cudaFuncSetAttribute(hgemm<0>, cudaFuncAttributeMaxDynamicSharedMemorySize, SMEM_BYTES);
    cudaFuncSetAttribute(hgemm<3>, cudaFuncAttributeMaxDynamicSharedMemorySize, SMEM_BYTES);
    cudaFuncSetAttribute(hgemm<4>, cudaFuncAttributeMaxDynamicSharedMemorySize, SMEM_BYTES);

    // 0) operand prep
    xsplit_kernel<<<SEQ * DM / (256 * 4), 256>>>(x);
    wtrans_kernel<<<dim3(DM / 32, DM / 32, 3), dim3(32, 8)>>>(Wq, Wk, Wv);

    // 1) projections Q/K/V (z selects weight + destination)
    hgemm<0><<<dim3(DM / TN, SEQ / TM, 3), NTHREADS, SMEM_BYTES>>>(nullptr);

    // 2) causal scores (lower-triangular blocks only)
    const int nTri = (SEQ / TM) * (SEQ / TM + 1) / 2;   // 528
    hgemm<3><<<nTri, NTHREADS, SMEM_BYTES>>>(nullptr);

    // 3) softmax -> P hi/lo
    softmax_kernel<<<SEQ, 256>>>();

    // 4) O = P @ V
    hgemm<4><<<dim3(DM / TN, SEQ / TM), NTHREADS, SMEM_BYTES>>>(out);
}

// round 7
// speedup vs baseline: 1.3121x; 1.1198x over previous
#include <cuda_runtime.h>
#include <cuda_bf16.h>
#include <math.h>
#include <stdint.h>

#define SEQ 4096
#define DM  1024
#define TM  128
#define TN  128
#define BK  32

#define NTHREADS 256

// PV split-K: 8 chunks (= 256 k-elements) per segment
#define SEGCH 8

// smem buffer layout (per stage): Ahi[128*80B] Alo Bhi Blo
#define A_PITCH  80        // bytes per row (64B data + 16B pad) -> conflict-free ldmatrix
#define AHI_OFF  0
#define ALO_OFF  10240
#define BHI_OFF  20480
#define BLO_OFF  30720
#define BUFB     40960
#define SMEM_BYTES (2 * BUFB)

// ---------------- scratch (device globals; allocation-free) ----------------
__device__ __nv_bfloat16 g_Xhi[SEQ * DM],  g_Xlo[SEQ * DM];
__device__ __nv_bfloat16 g_Qhi[SEQ * DM],  g_Qlo[SEQ * DM];
__device__ __nv_bfloat16 g_Khi[SEQ * DM],  g_Klo[SEQ * DM];
__device__ __nv_bfloat16 g_Vhi[SEQ * DM],  g_Vlo[SEQ * DM];
__device__ __nv_bfloat16 g_Wthi[3 * DM * DM], g_Wtlo[3 * DM * DM]; // W^T [n][k]
__device__ __nv_bfloat16 g_Phi[(size_t)SEQ * SEQ], g_Plo[(size_t)SEQ * SEQ];
__device__ float         g_S  [(size_t)SEQ * SEQ];

// ---------------- PTX helpers (baseline PTX only; no arch-'a' features) ----
__device__ __forceinline__ uint32_t smem_u32(const void* p) {
    uint32_t a;
    asm("{ .reg .u64 t; cvta.to.shared.u64 t, %1; cvt.u32.u64 %0, t; }" : "=r"(a) : "l"(p));
    return a;
}

#define CP16(dst, src) \
    asm volatile("cp.async.cg.shared.global [%0], [%1], 16;" :: "r"(dst), "l"(src) : "memory")
#define CP_COMMIT() asm volatile("cp.async.commit_group;" ::: "memory")
#define CP_WAIT(n)  asm volatile("cp.async.wait_group %0;" :: "n"(n) : "memory")

#define LDSM_X4(r, addr) \
    asm volatile("ldmatrix.sync.aligned.m8n8.x4.shared.b16 {%0,%1,%2,%3}, [%4];" \
        : "=r"((r)[0]), "=r"((r)[1]), "=r"((r)[2]), "=r"((r)[3]) : "r"(addr))
#define LDSM_X4T(r, addr) \
    asm volatile("ldmatrix.sync.aligned.m8n8.x4.trans.shared.b16 {%0,%1,%2,%3}, [%4];" \
        : "=r"((r)[0]), "=r"((r)[1]), "=r"((r)[2]), "=r"((r)[3]) : "r"(addr))

#define MMA_BF16(d, a, b0, b1) \
    asm volatile("mma.sync.aligned.m16n8k16.row.col.f32.bf16.bf16.f32 " \
        "{%0,%1,%2,%3}, {%4,%5,%6,%7}, {%8,%9}, {%0,%1,%2,%3};" \
        : "+f"((d)[0]), "+f"((d)[1]), "+f"((d)[2]), "+f"((d)[3]) \
        : "r"((a)[0]), "r"((a)[1]), "r"((a)[2]), "r"((a)[3]), "r"(b0), "r"(b1))

// ---------------- split helpers ----------------
__device__ __forceinline__ void split1(float v, __nv_bfloat16& h, __nv_bfloat16& l) {
    h = __float2bfloat16(v);
    l = __float2bfloat16(v - __bfloat162float(h));
}
__device__ __forceinline__ void split2(float x, float y, uint32_t& hu, uint32_t& lu) {
    __nv_bfloat162 h, l;
    h.x = __float2bfloat16(x);
    h.y = __float2bfloat16(y);
    l.x = __float2bfloat16(x - __bfloat162float(h.x));
    l.y = __float2bfloat16(y - __bfloat162float(h.y));
    hu = *reinterpret_cast<uint32_t*>(&h);
    lu = *reinterpret_cast<uint32_t*>(&l);
}

// ---------------------------------------------------------------------------
// X split: fp32 -> hi/lo bf16
// ---------------------------------------------------------------------------
__global__ __launch_bounds__(256) void xsplit_kernel(const float* __restrict__ x)
{
    int i = (blockIdx.x * 256 + threadIdx.x) * 4;
    float4 v = *(const float4*)(x + i);
    uint32_t h0, l0, h1, l1;
    split2(v.x, v.y, h0, l0);
    split2(v.z, v.w, h1, l1);
    *(uint2*)(g_Xhi + i) = make_uint2(h0, h1);
    *(uint2*)(g_Xlo + i) = make_uint2(l0, l1);
}

// ---------------------------------------------------------------------------
// W transpose + split: W [k][n] fp32 -> Wt hi/lo [n][k] bf16
// ---------------------------------------------------------------------------
__global__ __launch_bounds__(256) void wtrans_kernel(
    const float* __restrict__ Wq, const float* __restrict__ Wk, const float* __restrict__ Wv)
{
    __shared__ float t[32][33];
    const float* W = (blockIdx.z == 0) ? Wq : (blockIdx.z == 1) ? Wk : Wv;
    const size_t zoff = (size_t)blockIdx.z * DM * DM;
    const int n0 = blockIdx.x * 32, k0 = blockIdx.y * 32;
    const int tx = threadIdx.x, ty = threadIdx.y;  // (32, 8)

#pragma unroll
    for (int j = 0; j < 32; j += 8)
        t[ty + j][tx] = W[(size_t)(k0 + ty + j) * DM + n0 + tx];
    __syncthreads();
#pragma unroll
    for (int j = 0; j < 32; j += 8) {
        float v = t[tx][ty + j];
        __nv_bfloat16 h, l; split1(v, h, l);
        size_t o = zoff + (size_t)(n0 + ty + j) * DM + k0 + tx;
        g_Wthi[o] = h; g_Wtlo[o] = l;
    }
}

// ---------------------------------------------------------------------------
// Unified split-bf16 mma.sync GEMM. 128x128 CTA tile, 8 warps of 32x64, BK=32,
// cp.async double-buffered, 2 CTAs/SM (128-reg cap).
//  MODE 0: proj  (z = blockIdx.z + zbase: 0=Q,1=K,2=V). A=Xhi/lo, B=Wt[z].
//  MODE 3: scores. A=Qhi/lo, B=Khi/lo. tri grid; out g_S fp32 (scaled+masked).
//  MODE 4: PV split-K. A=Phi/lo, B=Vhi/lo [k][n]. 8-chunk segments,
//          atomicAdd accumulation into zeroed Oext.
// ---------------------------------------------------------------------------
template<int MODE>
__global__ __launch_bounds__(NTHREADS, 2) void hgemm(float* __restrict__ Oext, int zbase)
{
    extern __shared__ char smem[];
    const uint32_t sb = smem_u32(smem);
    const int tid  = threadIdx.x;
    const int wid  = tid >> 5;
    const int lane = tid & 31;
    const int wr   = wid & 3;        // warp row (32 rows)
    const int wc   = wid >> 2;       // warp col (64 cols)

    int m0, n0, br = 0, bc = 0;
    int cbeg = 0, cend = 0;
    if (MODE == 3) {
        int i = (int)blockIdx.x;
        br = (int)((sqrtf(8.0f * (float)i + 1.0f) - 1.0f) * 0.5f);
        while ((br + 1) * (br + 2) / 2 <= i) br++;
        while (br * (br + 1) / 2 > i)        br--;
        bc = i - br * (br + 1) / 2;
        m0 = br * TM; n0 = bc * TN;
        cbeg = 0; cend = DM / BK;
    } else if (MODE == 4) {
        // segment decode: per row i there are 8*ceil((i+1)/2) segments;
        // S(i) = floor((i+1)^2/4) cumulative segs per column-slice.
        const int idx = (int)blockIdx.x;
        const int q = idx >> 3;
        int i = (int)(2.0f * sqrtf((float)q));
        if (i > 31) i = 31;
        if (i < 0)  i = 0;
        while (i < 31 && ((i + 2) * (i + 2)) / 4 <= q) i++;
        while (i > 0  && ((i + 1) * (i + 1)) / 4 > q)  i--;
        const int u   = idx - 8 * (((i + 1) * (i + 1)) / 4);
        const int seg = u >> 3;
        const int j   = u & 7;
        m0 = i * TM; n0 = j * TN;
        cbeg = seg * SEGCH;
        const int nch_tot = 4 * (i + 1);
        cend = (cbeg + SEGCH < nch_tot) ? (cbeg + SEGCH) : nch_tot;
    } else {
        m0 = blockIdx.y * TM; n0 = blockIdx.x * TN;
        cbeg = 0; cend = DM / BK;
    }

    const __nv_bfloat16 *Ah, *Al, *Bh, *Bl;
    int lda, ldb;
    int z = 0;
    if (MODE == 0) {
        z = (int)blockIdx.z + zbase;
        Ah = g_Xhi; Al = g_Xlo; lda = DM; ldb = DM;
        Bh = g_Wthi + (size_t)z * DM * DM;
        Bl = g_Wtlo + (size_t)z * DM * DM;
    } else if (MODE == 3) {
        Ah = g_Qhi; Al = g_Qlo; lda = DM; ldb = DM;
        Bh = g_Khi; Bl = g_Klo;
    } else {
        Ah = g_Phi; Al = g_Plo; lda = SEQ; ldb = DM;
        Bh = g_Vhi; Bl = g_Vlo;   // [k][n], n contiguous
    }

    float acc[2][8][4];
#pragma unroll
    for (int mi = 0; mi < 2; mi++)
#pragma unroll
        for (int nf = 0; nf < 8; nf++)
#pragma unroll
            for (int q2 = 0; q2 < 4; q2++) acc[mi][nf][q2] = 0.0f;

    // ---- chunk loader
    auto load_chunk = [&](int c) {
        const int k0  = c * BK;
        const uint32_t base = sb + (uint32_t)(c & 1) * BUFB;
        if (MODE == 4) {
            // A: 128 rows x 32 k (4 chunks of 16B)
            for (int u2 = tid; u2 < 512; u2 += NTHREADS) {
                int row = u2 >> 2, ch = u2 & 3;
                size_t go = (size_t)(m0 + row) * lda + k0 + ch * 8;
                uint32_t da = base + AHI_OFF + row * A_PITCH + ch * 16;
                CP16(da,           Ah + go);
                CP16(da + ALO_OFF, Al + go);
            }
            // B: 32 k-rows x 128 n, XOR-swizzled chunks
            for (int u2 = tid; u2 < 512; u2 += NTHREADS) {
                int k = u2 >> 4, ch = u2 & 15;
                size_t go = (size_t)(k0 + k) * ldb + n0 + ch * 8;
                uint32_t db = base + BHI_OFF + k * 256 + ((ch ^ (k & 7)) << 4);
                CP16(db,                       Bh + go);
                CP16(db + (BLO_OFF - BHI_OFF), Bl + go);
            }
        } else {
            for (int u2 = tid; u2 < 512; u2 += NTHREADS) {
                int row = u2 >> 2, ch = u2 & 3;
                size_t ga = (size_t)(m0 + row) * lda + k0 + ch * 8;
                size_t gb = (size_t)(n0 + row) * ldb + k0 + ch * 8;
                uint32_t da = base + AHI_OFF + row * A_PITCH + ch * 16;
                uint32_t db = base + BHI_OFF + row * A_PITCH + ch * 16;
                CP16(da,           Ah + ga);
                CP16(da + ALO_OFF, Al + ga);
                CP16(db,           Bh + gb);
                CP16(db + (BLO_OFF - BHI_OFF), Bl + gb);
            }
        }
    };

    load_chunk(cbeg);
    CP_COMMIT();

    for (int c = cbeg; c < cend; c++) {
        if (c + 1 < cend) { load_chunk(c + 1); CP_COMMIT(); CP_WAIT(1); }
        else              { CP_WAIT(0); }
        __syncthreads();

        const uint32_t base = sb + (uint32_t)(c & 1) * BUFB;
#pragma unroll
        for (int ks = 0; ks < 2; ks++) {
            uint32_t ah[2][4], al[2][4];
#pragma unroll
            for (int mi = 0; mi < 2; mi++) {
                uint32_t aaddr = base + AHI_OFF
                    + (wr * 32 + mi * 16 + (lane & 15)) * A_PITCH
                    + (ks * 2 + (lane >> 4)) * 16;
                LDSM_X4(ah[mi], aaddr);
                LDSM_X4(al[mi], aaddr + ALO_OFF);
            }
            // B fragments: two n-tiles per ldmatrix.x4
#pragma unroll
            for (int nfp = 0; nfp < 4; nfp++) {
                uint32_t bh[4], bl[4];
                if (MODE == 4) {
                    int klo    = ks * 16 + (lane & 15);
                    int cchunk = wc * 8 + nfp * 2 + ((lane >> 4) & 1);
                    uint32_t baddr = base + BHI_OFF + klo * 256
                        + ((cchunk ^ (klo & 7)) << 4);
                    LDSM_X4T(bh, baddr);
                    LDSM_X4T(bl, baddr + (BLO_OFF - BHI_OFF));
                } else {
                    uint32_t baddr = base + BHI_OFF
                        + (wc * 64 + nfp * 16 + (lane & 7) + ((lane >> 4) & 1) * 8) * A_PITCH
                        + ks * 32 + ((lane >> 3) & 1) * 16;
                    LDSM_X4(bh, baddr);
                    LDSM_X4(bl, baddr + (BLO_OFF - BHI_OFF));
                }
#pragma unroll
                for (int mi = 0; mi < 2; mi++) {
                    MMA_BF16(acc[mi][nfp * 2],     ah[mi], bh[0], bh[1]);
                    MMA_BF16(acc[mi][nfp * 2],     ah[mi], bl[0], bl[1]);
                    MMA_BF16(acc[mi][nfp * 2],     al[mi], bh[0], bh[1]);
                    MMA_BF16(acc[mi][nfp * 2 + 1], ah[mi], bh[2], bh[3]);
                    MMA_BF16(acc[mi][nfp * 2 + 1], ah[mi], bl[2], bl[3]);
                    MMA_BF16(acc[mi][nfp * 2 + 1], al[mi], bh[2], bh[3]);
                }
            }
        }
        __syncthreads();
    }

    // ---- epilogue
    const int rb = m0 + wr * 32 + (lane >> 2);
    const int cb = n0 + wc * 64 + 2 * (lane & 3);
    const float scale = 0.03125f;   // 1/sqrt(1024), MODE 3 only

#pragma unroll
    for (int mi = 0; mi < 2; mi++) {
#pragma unroll
        for (int nf = 0; nf < 8; nf++) {
            int r0 = rb + mi * 16;
            int cc = cb + nf * 8;
            float v00 = acc[mi][nf][0], v01 = acc[mi][nf][1];
            float v10 = acc[mi][nf][2], v11 = acc[mi][nf][3];
            if (MODE == 0) {
                __nv_bfloat16* Oh = (z == 0) ? g_Qhi : (z == 1) ? g_Khi : g_Vhi;
                __nv_bfloat16* Ol = (z == 0) ? g_Qlo : (z == 1) ? g_Klo : g_Vlo;
                uint32_t h, l;
                split2(v00, v01, h, l);
                *(uint32_t*)(Oh + (size_t)r0 * DM + cc) = h;
                *(uint32_t*)(Ol + (size_t)r0 * DM + cc) = l;
                split2(v10, v11, h, l);
                *(uint32_t*)(Oh + (size_t)(r0 + 8) * DM + cc) = h;
                *(uint32_t*)(Ol + (size_t)(r0 + 8) * DM + cc) = l;
            } else if (MODE == 3) {
                if (br == bc) {
                    float* s0 = g_S + (size_t)r0 * SEQ + cc;
                    s0[0] = (cc + 0 <= r0) ? v00 * scale : -INFINITY;
                    s0[1] = (cc + 1 <= r0) ? v01 * scale : -INFINITY;
                    float* s1 = g_S + (size_t)(r0 + 8) * SEQ + cc;
                    s1[0] = (cc + 0 <= r0 + 8) ? v10 * scale : -INFINITY;
                    s1[1] = (cc + 1 <= r0 + 8) ? v11 * scale : -INFINITY;
                } else {
                    *(float2*)(g_S + (size_t)r0 * SEQ + cc)       = make_float2(v00 * scale, v01 * scale);
                    *(float2*)(g_S + (size_t)(r0 + 8) * SEQ + cc) = make_float2(v10 * scale, v11 * scale);
                }
            } else {
                float* p0 = Oext + (size_t)r0 * DM + cc;
                float* p1 = Oext + (size_t)(r0 + 8) * DM + cc;
                atomicAdd(p0,     v00);
                atomicAdd(p0 + 1, v01);
                atomicAdd(p1,     v10);
                atomicAdd(p1 + 1, v11);
            }
        }
    }
}

// ---------------------------------------------------------------------------
// Row softmax over g_S; emits P hi/lo bf16. Row r covers [0, roundup128(r+1)).
// ---------------------------------------------------------------------------
__global__ __launch_bounds__(256) void softmax_kernel()
{
    const int r   = (int)blockIdx.x;
    const int L   = (((r >> 7) + 1) << 7);
    const float* row = g_S + (size_t)r * SEQ;
    const int tid = threadIdx.x;
    __shared__ float red[256];

    float v[16];
    int   cnt = 0;
    float mx  = -INFINITY;
    for (int c = tid; c < L; c += 256) {
        float t = row[c];
        v[cnt++] = t;
        mx = fmaxf(mx, t);
    }
    red[tid] = mx;
    __syncthreads();
#pragma unroll
    for (int s = 128; s > 0; s >>= 1) {
        if (tid < s) red[tid] = fmaxf(red[tid], red[tid + s]);
        __syncthreads();
    }
    mx = red[0];
    __syncthreads();

    float sum = 0.0f;
    for (int j = 0; j < cnt; j++) {
        v[j] = expf(v[j] - mx);
        sum += v[j];
    }
    red[tid] = sum;
    __syncthreads();
#pragma unroll
    for (int s = 128; s > 0; s >>= 1) {
        if (tid < s) red[tid] += red[tid + s];
        __syncthreads();
    }
    const float rinv = 1.0f / red[0];

    cnt = 0;
    for (int c = tid; c < L; c += 256) {
        float p = v[cnt++] * rinv;
        __nv_bfloat16 h, l; split1(p, h, l);
        g_Phi[(size_t)r * SEQ + c] = h;
        g_Plo[(size_t)r * SEQ + c] = l;
    }
}

// ---------------------------------------------------------------------------
extern "C" void kernel_launch(void* const* d_in, const int* in_sizes, int n_in,
                              void* d_out, int out_size)
{
    const float* x  = (const float*)d_in[0];
    const float* Wq = (const float*)d_in[1];
    const float* Wk = (const float*)d_in[2];
    const float* Wv = (const float*)d_in[3];
    float* out = (float*)d_out;
    (void)in_sizes; (void)n_in;

    cudaFuncSetAttribute(hgemm<0>, cudaFuncAttributeMaxDynamicSharedMemorySize, SMEM_BYTES);
    cudaFuncSetAttribute(hgemm<3>, cudaFuncAttributeMaxDynamicSharedMemorySize, SMEM_BYTES);
    cudaFuncSetAttribute(hgemm<4>, cudaFuncAttributeMaxDynamicSharedMemorySize, SMEM_BYTES);

    // side stream + fork/join events (created per call; tiny host resources)
    cudaStream_t s2;
    cudaStreamCreate(&s2);
    cudaEvent_t eFork, eJoin;
    cudaEventCreateWithFlags(&eFork, cudaEventDisableTiming);
    cudaEventCreateWithFlags(&eJoin, cudaEventDisableTiming);

    // 0) operand prep (main stream) + zero output for PV atomics
    xsplit_kernel<<<SEQ * DM / (256 * 4), 256>>>(x);
    wtrans_kernel<<<dim3(DM / 32, DM / 32, 3), dim3(32, 8)>>>(Wq, Wk, Wv);
    cudaMemsetAsync(out, 0, (size_t)out_size * sizeof(float), 0);

    // fork: V projection on side stream, overlapped with Q,K proj + scores
    cudaEventRecord(eFork, 0);
    cudaStreamWaitEvent(s2, eFork, 0);
    hgemm<0><<<dim3(DM / TN, SEQ / TM, 1), NTHREADS, SMEM_BYTES, s2>>>(nullptr, 2);  // V
    cudaEventRecord(eJoin, s2);

    // 1) Q,K projections (main stream)
    hgemm<0><<<dim3(DM / TN, SEQ / TM, 2), NTHREADS, SMEM_BYTES>>>(nullptr, 0);

    // 2) causal scores (lower-triangular blocks only)
    const int nTri = (SEQ / TM) * (SEQ / TM + 1) / 2;   // 528
    hgemm<3><<<nTri, NTHREADS, SMEM_BYTES>>>(nullptr, 0);

    // 3) softmax -> P hi/lo
    softmax_kernel<<<SEQ, 256>>>();

    // join: PV needs V
    cudaStreamWaitEvent(0, eJoin, 0);

    // 4) O = P @ V, split-K segments (8*floor((32+1)^2/4) = 2176 CTAs)
    const int nSeg = 8 * ((33 * 33) / 4);   // 2176
    hgemm<4><<<nSeg, NTHREADS, SMEM_BYTES>>>(out, 0);
}

// round 8
// speedup vs baseline: 1.4029x; 1.0692x over previous
#include <cuda_runtime.h>
#include <cuda_bf16.h>
#include <cuda_fp16.h>
#include <math.h>
#include <stdint.h>

#define SEQ 4096
#define DM  1024
#define TM  128
#define TN  128
#define BK  32

#define NTHREADS 256

// PV split-K: 8 chunks (= 256 k-elements) per segment
#define SEGCH 8

// smem buffer layout (per stage): Ahi[128*80B] Alo Bhi Blo
#define A_PITCH  80        // bytes per row (64B data + 16B pad) -> conflict-free ldmatrix
#define AHI_OFF  0
#define ALO_OFF  10240
#define BHI_OFF  20480
#define BLO_OFF  30720
#define BUFB     40960
#define SMEM_BYTES (2 * BUFB)

// ---------------- scratch (device globals; allocation-free) ----------------
__device__ __nv_bfloat16 g_Xhi[SEQ * DM],  g_Xlo[SEQ * DM];
__device__ __nv_bfloat16 g_Qhi[SEQ * DM],  g_Qlo[SEQ * DM];
__device__ __nv_bfloat16 g_Khi[SEQ * DM],  g_Klo[SEQ * DM];
__device__ __half        g_Vhi[SEQ * DM],  g_Vlo[SEQ * DM];   // fp16 for 2-pass PV
__device__ __nv_bfloat16 g_Wthi[3 * DM * DM], g_Wtlo[3 * DM * DM]; // W^T [n][k]
__device__ __half        g_P  [(size_t)SEQ * SEQ];             // fp16 softmax output
__device__ float         g_S  [(size_t)SEQ * SEQ];

// ---------------- PTX helpers (baseline PTX only; no arch-'a' features) ----
__device__ __forceinline__ uint32_t smem_u32(const void* p) {
    uint32_t a;
    asm("{ .reg .u64 t; cvta.to.shared.u64 t, %1; cvt.u32.u64 %0, t; }" : "=r"(a) : "l"(p));
    return a;
}

#define CP16(dst, src) \
    asm volatile("cp.async.cg.shared.global [%0], [%1], 16;" :: "r"(dst), "l"(src) : "memory")
#define CP_COMMIT() asm volatile("cp.async.commit_group;" ::: "memory")
#define CP_WAIT(n)  asm volatile("cp.async.wait_group %0;" :: "n"(n) : "memory")

#define LDSM_X4(r, addr) \
    asm volatile("ldmatrix.sync.aligned.m8n8.x4.shared.b16 {%0,%1,%2,%3}, [%4];" \
        : "=r"((r)[0]), "=r"((r)[1]), "=r"((r)[2]), "=r"((r)[3]) : "r"(addr))
#define LDSM_X4T(r, addr) \
    asm volatile("ldmatrix.sync.aligned.m8n8.x4.trans.shared.b16 {%0,%1,%2,%3}, [%4];" \
        : "=r"((r)[0]), "=r"((r)[1]), "=r"((r)[2]), "=r"((r)[3]) : "r"(addr))

#define MMA_BF16(d, a, b0, b1) \
    asm volatile("mma.sync.aligned.m16n8k16.row.col.f32.bf16.bf16.f32 " \
        "{%0,%1,%2,%3}, {%4,%5,%6,%7}, {%8,%9}, {%0,%1,%2,%3};" \
        : "+f"((d)[0]), "+f"((d)[1]), "+f"((d)[2]), "+f"((d)[3]) \
        : "r"((a)[0]), "r"((a)[1]), "r"((a)[2]), "r"((a)[3]), "r"(b0), "r"(b1))

#define MMA_F16(d, a, b0, b1) \
    asm volatile("mma.sync.aligned.m16n8k16.row.col.f32.f16.f16.f32 " \
        "{%0,%1,%2,%3}, {%4,%5,%6,%7}, {%8,%9}, {%0,%1,%2,%3};" \
        : "+f"((d)[0]), "+f"((d)[1]), "+f"((d)[2]), "+f"((d)[3]) \
        : "r"((a)[0]), "r"((a)[1]), "r"((a)[2]), "r"((a)[3]), "r"(b0), "r"(b1))

// ---------------- split helpers ----------------
__device__ __forceinline__ void split1(float v, __nv_bfloat16& h, __nv_bfloat16& l) {
    h = __float2bfloat16(v);
    l = __float2bfloat16(v - __bfloat162float(h));
}
__device__ __forceinline__ void split2(float x, float y, uint32_t& hu, uint32_t& lu) {
    __nv_bfloat162 h, l;
    h.x = __float2bfloat16(x);
    h.y = __float2bfloat16(y);
    l.x = __float2bfloat16(x - __bfloat162float(h.x));
    l.y = __float2bfloat16(y - __bfloat162float(h.y));
    hu = *reinterpret_cast<uint32_t*>(&h);
    lu = *reinterpret_cast<uint32_t*>(&l);
}
__device__ __forceinline__ void splitH2(float x, float y, uint32_t& hu, uint32_t& lu) {
    __half2 h, l;
    h.x = __float2half_rn(x);
    h.y = __float2half_rn(y);
    l.x = __float2half_rn(x - __half2float(h.x));
    l.y = __float2half_rn(y - __half2float(h.y));
    hu = *reinterpret_cast<uint32_t*>(&h);
    lu = *reinterpret_cast<uint32_t*>(&l);
}

// ---------------------------------------------------------------------------
// X split: fp32 -> hi/lo bf16
// ---------------------------------------------------------------------------
__global__ __launch_bounds__(256) void xsplit_kernel(const float* __restrict__ x)
{
    int i = (blockIdx.x * 256 + threadIdx.x) * 4;
    float4 v = *(const float4*)(x + i);
    uint32_t h0, l0, h1, l1;
    split2(v.x, v.y, h0, l0);
    split2(v.z, v.w, h1, l1);
    *(uint2*)(g_Xhi + i) = make_uint2(h0, h1);
    *(uint2*)(g_Xlo + i) = make_uint2(l0, l1);
}

// ---------------------------------------------------------------------------
// W transpose + split: W [k][n] fp32 -> Wt hi/lo [n][k] bf16
// ---------------------------------------------------------------------------
__global__ __launch_bounds__(256) void wtrans_kernel(
    const float* __restrict__ Wq, const float* __restrict__ Wk, const float* __restrict__ Wv)
{
    __shared__ float t[32][33];
    const float* W = (blockIdx.z == 0) ? Wq : (blockIdx.z == 1) ? Wk : Wv;
    const size_t zoff = (size_t)blockIdx.z * DM * DM;
    const int n0 = blockIdx.x * 32, k0 = blockIdx.y * 32;
    const int tx = threadIdx.x, ty = threadIdx.y;  // (32, 8)

#pragma unroll
    for (int j = 0; j < 32; j += 8)
        t[ty + j][tx] = W[(size_t)(k0 + ty + j) * DM + n0 + tx];
    __syncthreads();
#pragma unroll
    for (int j = 0; j < 32; j += 8) {
        float v = t[tx][ty + j];
        __nv_bfloat16 h, l; split1(v, h, l);
        size_t o = zoff + (size_t)(n0 + ty + j) * DM + k0 + tx;
        g_Wthi[o] = h; g_Wtlo[o] = l;
    }
}

// ---------------------------------------------------------------------------
// Unified split mma.sync GEMM. 128x128 CTA tile, 8 warps of 32x64, BK=32,
// cp.async double-buffered, 2 CTAs/SM (128-reg cap).
//  MODE 0: proj (z=blockIdx.z+zbase: 0=Q,1=K,2=V). bf16 3-pass.
//          z<2 out split bf16; z==2 out split fp16.
//  MODE 3: scores. bf16 3-pass. tri grid; out g_S fp32 (scaled+masked).
//  MODE 4: PV split-K. fp16 2-pass (A=P fp16 single, B=V fp16 hi/lo [k][n]).
//          atomicAdd accumulation into zeroed Oext.
// ---------------------------------------------------------------------------
template<int MODE>
__global__ __launch_bounds__(NTHREADS, 2) void hgemm(float* __restrict__ Oext, int zbase)
{
    extern __shared__ char smem[];
    const uint32_t sb = smem_u32(smem);
    const int tid  = threadIdx.x;
    const int wid  = tid >> 5;
    const int lane = tid & 31;
    const int wr   = wid & 3;        // warp row (32 rows)
    const int wc   = wid >> 2;       // warp col (64 cols)

    int m0, n0, br = 0, bc = 0;
    int cbeg = 0, cend = 0;
    if (MODE == 3) {
        int i = (int)blockIdx.x;
        br = (int)((sqrtf(8.0f * (float)i + 1.0f) - 1.0f) * 0.5f);
        while ((br + 1) * (br + 2) / 2 <= i) br++;
        while (br * (br + 1) / 2 > i)        br--;
        bc = i - br * (br + 1) / 2;
        m0 = br * TM; n0 = bc * TN;
        cbeg = 0; cend = DM / BK;
    } else if (MODE == 4) {
        // segment decode: per row i there are 8*ceil((i+1)/2) segments;
        // S(i) = floor((i+1)^2/4) cumulative segs per column-slice.
        const int idx = (int)blockIdx.x;
        const int q = idx >> 3;
        int i = (int)(2.0f * sqrtf((float)q));
        if (i > 31) i = 31;
        if (i < 0)  i = 0;
        while (i < 31 && ((i + 2) * (i + 2)) / 4 <= q) i++;
        while (i > 0  && ((i + 1) * (i + 1)) / 4 > q)  i--;
        const int u   = idx - 8 * (((i + 1) * (i + 1)) / 4);
        const int seg = u >> 3;
        const int j   = u & 7;
        m0 = i * TM; n0 = j * TN;
        cbeg = seg * SEGCH;
        const int nch_tot = 4 * (i + 1);
        cend = (cbeg + SEGCH < nch_tot) ? (cbeg + SEGCH) : nch_tot;
    } else {
        m0 = blockIdx.y * TM; n0 = blockIdx.x * TN;
        cbeg = 0; cend = DM / BK;
    }

    const __nv_bfloat16 *Ah, *Al, *Bh, *Bl;
    int lda, ldb;
    int z = 0;
    if (MODE == 0) {
        z = (int)blockIdx.z + zbase;
        Ah = g_Xhi; Al = g_Xlo; lda = DM; ldb = DM;
        Bh = g_Wthi + (size_t)z * DM * DM;
        Bl = g_Wtlo + (size_t)z * DM * DM;
    } else if (MODE == 3) {
        Ah = g_Qhi; Al = g_Qlo; lda = DM; ldb = DM;
        Bh = g_Khi; Bl = g_Klo;
    } else {
        Ah = reinterpret_cast<const __nv_bfloat16*>(g_P);  Al = nullptr;
        lda = SEQ; ldb = DM;
        Bh = reinterpret_cast<const __nv_bfloat16*>(g_Vhi);
        Bl = reinterpret_cast<const __nv_bfloat16*>(g_Vlo);  // [k][n], n contiguous
    }

    float acc[2][8][4];
#pragma unroll
    for (int mi = 0; mi < 2; mi++)
#pragma unroll
        for (int nf = 0; nf < 8; nf++)
#pragma unroll
            for (int q2 = 0; q2 < 4; q2++) acc[mi][nf][q2] = 0.0f;

    // ---- chunk loader
    auto load_chunk = [&](int c) {
        const int k0  = c * BK;
        const uint32_t base = sb + (uint32_t)(c & 1) * BUFB;
        if (MODE == 4) {
            // A (P, fp16 single): 128 rows x 32 k
            for (int u2 = tid; u2 < 512; u2 += NTHREADS) {
                int row = u2 >> 2, ch = u2 & 3;
                size_t go = (size_t)(m0 + row) * lda + k0 + ch * 8;
                uint32_t da = base + AHI_OFF + row * A_PITCH + ch * 16;
                CP16(da, Ah + go);
            }
            // B (V hi/lo): 32 k-rows x 128 n, XOR-swizzled chunks
            for (int u2 = tid; u2 < 512; u2 += NTHREADS) {
                int k = u2 >> 4, ch = u2 & 15;
                size_t go = (size_t)(k0 + k) * ldb + n0 + ch * 8;
                uint32_t db = base + BHI_OFF + k * 256 + ((ch ^ (k & 7)) << 4);
                CP16(db,                       Bh + go);
                CP16(db + (BLO_OFF - BHI_OFF), Bl + go);
            }
        } else {
            for (int u2 = tid; u2 < 512; u2 += NTHREADS) {
                int row = u2 >> 2, ch = u2 & 3;
                size_t ga = (size_t)(m0 + row) * lda + k0 + ch * 8;
                size_t gb = (size_t)(n0 + row) * ldb + k0 + ch * 8;
                uint32_t da = base + AHI_OFF + row * A_PITCH + ch * 16;
                uint32_t db = base + BHI_OFF + row * A_PITCH + ch * 16;
                CP16(da,           Ah + ga);
                CP16(da + ALO_OFF, Al + ga);
                CP16(db,           Bh + gb);
                CP16(db + (BLO_OFF - BHI_OFF), Bl + gb);
            }
        }
    };

    load_chunk(cbeg);
    CP_COMMIT();

    for (int c = cbeg; c < cend; c++) {
        if (c + 1 < cend) { load_chunk(c + 1); CP_COMMIT(); CP_WAIT(1); }
        else              { CP_WAIT(0); }
        __syncthreads();

        const uint32_t base = sb + (uint32_t)(c & 1) * BUFB;
#pragma unroll
        for (int ks = 0; ks < 2; ks++) {
            uint32_t ah[2][4], al[2][4];
#pragma unroll
            for (int mi = 0; mi < 2; mi++) {
                uint32_t aaddr = base + AHI_OFF
                    + (wr * 32 + mi * 16 + (lane & 15)) * A_PITCH
                    + (ks * 2 + (lane >> 4)) * 16;
                LDSM_X4(ah[mi], aaddr);
                if (MODE != 4) LDSM_X4(al[mi], aaddr + ALO_OFF);
            }
            // B fragments: two n-tiles per ldmatrix.x4
#pragma unroll
            for (int nfp = 0; nfp < 4; nfp++) {
                uint32_t bh[4], bl[4];
                if (MODE == 4) {
                    int klo    = ks * 16 + (lane & 15);
                    int cchunk = wc * 8 + nfp * 2 + ((lane >> 4) & 1);
                    uint32_t baddr = base + BHI_OFF + klo * 256
                        + ((cchunk ^ (klo & 7)) << 4);
                    LDSM_X4T(bh, baddr);
                    LDSM_X4T(bl, baddr + (BLO_OFF - BHI_OFF));
                } else {
                    uint32_t baddr = base + BHI_OFF
                        + (wc * 64 + nfp * 16 + (lane & 7) + ((lane >> 4) & 1) * 8) * A_PITCH
                        + ks * 32 + ((lane >> 3) & 1) * 16;
                    LDSM_X4(bh, baddr);
                    LDSM_X4(bl, baddr + (BLO_OFF - BHI_OFF));
                }
#pragma unroll
                for (int mi = 0; mi < 2; mi++) {
                    if (MODE == 4) {
                        // fp16 2-pass: Ph*Vh + Ph*Vl
                        MMA_F16(acc[mi][nfp * 2],     ah[mi], bh[0], bh[1]);
                        MMA_F16(acc[mi][nfp * 2],     ah[mi], bl[0], bl[1]);
                        MMA_F16(acc[mi][nfp * 2 + 1], ah[mi], bh[2], bh[3]);
                        MMA_F16(acc[mi][nfp * 2 + 1], ah[mi], bl[2], bl[3]);
                    } else {
                        // bf16 3-pass
                        MMA_BF16(acc[mi][nfp * 2],     ah[mi], bh[0], bh[1]);
                        MMA_BF16(acc[mi][nfp * 2],     ah[mi], bl[0], bl[1]);
                        MMA_BF16(acc[mi][nfp * 2],     al[mi], bh[0], bh[1]);
                        MMA_BF16(acc[mi][nfp * 2 + 1], ah[mi], bh[2], bh[3]);
                        MMA_BF16(acc[mi][nfp * 2 + 1], ah[mi], bl[2], bl[3]);
                        MMA_BF16(acc[mi][nfp * 2 + 1], al[mi], bh[2], bh[3]);
                    }
                }
            }
        }
        __syncthreads();
    }

    // ---- epilogue
    const int rb = m0 + wr * 32 + (lane >> 2);
    const int cb = n0 + wc * 64 + 2 * (lane & 3);
    const float scale = 0.03125f;   // 1/sqrt(1024), MODE 3 only

#pragma unroll
    for (int mi = 0; mi < 2; mi++) {
#pragma unroll
        for (int nf = 0; nf < 8; nf++) {
            int r0 = rb + mi * 16;
            int cc = cb + nf * 8;
            float v00 = acc[mi][nf][0], v01 = acc[mi][nf][1];
            float v10 = acc[mi][nf][2], v11 = acc[mi][nf][3];
            if (MODE == 0) {
                if (z == 2) {
                    uint32_t h, l;
                    splitH2(v00, v01, h, l);
                    *(uint32_t*)(g_Vhi + (size_t)r0 * DM + cc) = h;
                    *(uint32_t*)(g_Vlo + (size_t)r0 * DM + cc) = l;
                    splitH2(v10, v11, h, l);
                    *(uint32_t*)(g_Vhi + (size_t)(r0 + 8) * DM + cc) = h;
                    *(uint32_t*)(g_Vlo + (size_t)(r0 + 8) * DM + cc) = l;
                } else {
                    __nv_bfloat16* Oh = (z == 0) ? g_Qhi : g_Khi;
                    __nv_bfloat16* Ol = (z == 0) ? g_Qlo : g_Klo;
                    uint32_t h, l;
                    split2(v00, v01, h, l);
                    *(uint32_t*)(Oh + (size_t)r0 * DM + cc) = h;
                    *(uint32_t*)(Ol + (size_t)r0 * DM + cc) = l;
                    split2(v10, v11, h, l);
                    *(uint32_t*)(Oh + (size_t)(r0 + 8) * DM + cc) = h;
                    *(uint32_t*)(Ol + (size_t)(r0 + 8) * DM + cc) = l;
                }
            } else if (MODE == 3) {
                if (br == bc) {
                    float* s0 = g_S + (size_t)r0 * SEQ + cc;
                    s0[0] = (cc + 0 <= r0) ? v00 * scale : -INFINITY;
                    s0[1] = (cc + 1 <= r0) ? v01 * scale : -INFINITY;
                    float* s1 = g_S + (size_t)(r0 + 8) * SEQ + cc;
                    s1[0] = (cc + 0 <= r0 + 8) ? v10 * scale : -INFINITY;
                    s1[1] = (cc + 1 <= r0 + 8) ? v11 * scale : -INFINITY;
                } else {
                    *(float2*)(g_S + (size_t)r0 * SEQ + cc)       = make_float2(v00 * scale, v01 * scale);
                    *(float2*)(g_S + (size_t)(r0 + 8) * SEQ + cc) = make_float2(v10 * scale, v11 * scale);
                }
            } else {
                float* p0 = Oext + (size_t)r0 * DM + cc;
                float* p1 = Oext + (size_t)(r0 + 8) * DM + cc;
                atomicAdd(p0,     v00);
                atomicAdd(p0 + 1, v01);
                atomicAdd(p1,     v10);
                atomicAdd(p1 + 1, v11);
            }
        }
    }
}

// ---------------------------------------------------------------------------
// Row softmax over g_S; emits P fp16. Row r covers [0, roundup128(r+1)).
// ---------------------------------------------------------------------------
__global__ __launch_bounds__(256) void softmax_kernel()
{
    const int r   = (int)blockIdx.x;
    const int L   = (((r >> 7) + 1) << 7);
    const float* row = g_S + (size_t)r * SEQ;
    const int tid = threadIdx.x;
    __shared__ float red[256];

    float v[16];
    int   cnt = 0;
    float mx  = -INFINITY;
    for (int c = tid; c < L; c += 256) {
        float t = row[c];
        v[cnt++] = t;
        mx = fmaxf(mx, t);
    }
    red[tid] = mx;
    __syncthreads();
#pragma unroll
    for (int s = 128; s > 0; s >>= 1) {
        if (tid < s) red[tid] = fmaxf(red[tid], red[tid + s]);
        __syncthreads();
    }
    mx = red[0];
    __syncthreads();

    float sum = 0.0f;
    for (int j = 0; j < cnt; j++) {
        v[j] = expf(v[j] - mx);
        sum += v[j];
    }
    red[tid] = sum;
    __syncthreads();
#pragma unroll
    for (int s = 128; s > 0; s >>= 1) {
        if (tid < s) red[tid] += red[tid + s];
        __syncthreads();
    }
    const float rinv = 1.0f / red[0];

    cnt = 0;
    for (int c = tid; c < L; c += 256) {
        float p = v[cnt++] * rinv;
        g_P[(size_t)r * SEQ + c] = __float2half_rn(p);
    }
}

// ---------------------------------------------------------------------------
extern "C" void kernel_launch(void* const* d_in, const int* in_sizes, int n_in,
                              void* d_out, int out_size)
{
    const float* x  = (const float*)d_in[0];
    const float* Wq = (const float*)d_in[1];
    const float* Wk = (const float*)d_in[2];
    const float* Wv = (const float*)d_in[3];
    float* out = (float*)d_out;
    (void)in_sizes; (void)n_in;

    cudaFuncSetAttribute(hgemm<0>, cudaFuncAttributeMaxDynamicSharedMemorySize, SMEM_BYTES);
    cudaFuncSetAttribute(hgemm<3>, cudaFuncAttributeMaxDynamicSharedMemorySize, SMEM_BYTES);
    cudaFuncSetAttribute(hgemm<4>, cudaFuncAttributeMaxDynamicSharedMemorySize, SMEM_BYTES);

    // side stream + fork/join events
    cudaStream_t s2;
    cudaStreamCreate(&s2);
    cudaEvent_t eFork, eJoin;
    cudaEventCreateWithFlags(&eFork, cudaEventDisableTiming);
    cudaEventCreateWithFlags(&eJoin, cudaEventDisableTiming);

    // 0) operand prep (main stream) + zero output for PV atomics
    xsplit_kernel<<<SEQ * DM / (256 * 4), 256>>>(x);
    wtrans_kernel<<<dim3(DM / 32, DM / 32, 3), dim3(32, 8)>>>(Wq, Wk, Wv);
    cudaMemsetAsync(out, 0, (size_t)out_size * sizeof(float), 0);

    // fork: V projection on side stream, overlapped with Q,K proj + scores
    cudaEventRecord(eFork, 0);
    cudaStreamWaitEvent(s2, eFork, 0);
    hgemm<0><<<dim3(DM / TN, SEQ / TM, 1), NTHREADS, SMEM_BYTES, s2>>>(nullptr, 2);  // V
    cudaEventRecord(eJoin, s2);

    // 1) Q,K projections (main stream)
    hgemm<0><<<dim3(DM / TN, SEQ / TM, 2), NTHREADS, SMEM_BYTES>>>(nullptr, 0);

    // 2) causal scores (lower-triangular blocks only)
    const int nTri = (SEQ / TM) * (SEQ / TM + 1) / 2;   // 528
    hgemm<3><<<nTri, NTHREADS, SMEM_BYTES>>>(nullptr, 0);

    // 3) softmax -> P fp16
    softmax_kernel<<<SEQ, 256>>>();

    // join: PV needs V
    cudaStreamWaitEvent(0, eJoin, 0);

    // 4) O = P @ V, split-K segments (2176 CTAs)
    const int nSeg = 8 * ((33 * 33) / 4);   // 2176
    hgemm<4><<<nSeg, NTHREADS, SMEM_BYTES>>>(out, 0);
}

// round 11
// speedup vs baseline: 1.7652x; 1.2583x over previous
#include <cuda_runtime.h>
#include <cuda_bf16.h>
#include <cuda_fp16.h>
#include <math.h>
#include <stdint.h>

#define SEQ 4096
#define DM  1024
#define TM  128
#define TN  128
#define BK  32

#define NTHREADS 256

// PV split-K: 8 chunks (= 256 k-elements) per segment
#define SEGCH 8

// smem per stage: A(single fp16)[128*80B]  Bhi  Blo
#define A_PITCH  80        // 64B data + 16B pad -> conflict-free ldmatrix
#define BHI_OFF  10240
#define BLO_OFF  20480
#define BUFB     30720
#define SMEM_BYTES (2 * BUFB)

// ---------------- scratch (device globals; allocation-free) ----------------
__device__ __half  g_Xh [SEQ * DM];                       // X single fp16
__device__ __half  g_Q  [SEQ * DM];                       // Q single fp16
__device__ __half  g_Kh [SEQ * DM],  g_Kl [SEQ * DM];     // K hi/lo fp16
__device__ __half  g_Vh [SEQ * DM],  g_Vl [SEQ * DM];     // V hi/lo fp16
__device__ __half  g_Wth[3 * DM * DM], g_Wtl[3 * DM * DM];// W^T [n][k] hi/lo fp16
__device__ __half  g_P  [(size_t)SEQ * SEQ];              // softmax out fp16
__device__ float   g_S  [(size_t)SEQ * SEQ];

// ---------------- PTX helpers (baseline PTX only) ----------------
__device__ __forceinline__ uint32_t smem_u32(const void* p) {
    uint32_t a;
    asm("{ .reg .u64 t; cvta.to.shared.u64 t, %1; cvt.u32.u64 %0, t; }" : "=r"(a) : "l"(p));
    return a;
}

#define CP16(dst, src) \
    asm volatile("cp.async.cg.shared.global [%0], [%1], 16;" :: "r"(dst), "l"(src) : "memory")
#define CP_COMMIT() asm volatile("cp.async.commit_group;" ::: "memory")
#define CP_WAIT(n)  asm volatile("cp.async.wait_group %0;" :: "n"(n) : "memory")

#define LDSM_X4(r, addr) \
    asm volatile("ldmatrix.sync.aligned.m8n8.x4.shared.b16 {%0,%1,%2,%3}, [%4];" \
        : "=r"((r)[0]), "=r"((r)[1]), "=r"((r)[2]), "=r"((r)[3]) : "r"(addr))
#define LDSM_X4T(r, addr) \
    asm volatile("ldmatrix.sync.aligned.m8n8.x4.trans.shared.b16 {%0,%1,%2,%3}, [%4];" \
        : "=r"((r)[0]), "=r"((r)[1]), "=r"((r)[2]), "=r"((r)[3]) : "r"(addr))

#define MMA_F16(d, a, b0, b1) \
    asm volatile("mma.sync.aligned.m16n8k16.row.col.f32.f16.f16.f32 " \
        "{%0,%1,%2,%3}, {%4,%5,%6,%7}, {%8,%9}, {%0,%1,%2,%3};" \
        : "+f"((d)[0]), "+f"((d)[1]), "+f"((d)[2]), "+f"((d)[3]) \
        : "r"((a)[0]), "r"((a)[1]), "r"((a)[2]), "r"((a)[3]), "r"(b0), "r"(b1))

// ---------------- fp16 split/pack helpers ----------------
__device__ __forceinline__ void splitH1(float v, __half& h, __half& l) {
    h = __float2half_rn(v);
    l = __float2half_rn(v - __half2float(h));
}
__device__ __forceinline__ void splitH2(float x, float y, uint32_t& hu, uint32_t& lu) {
    __half2 h, l;
    h.x = __float2half_rn(x);
    h.y = __float2half_rn(y);
    l.x = __float2half_rn(x - __half2float(h.x));
    l.y = __float2half_rn(y - __half2float(h.y));
    hu = *reinterpret_cast<uint32_t*>(&h);
    lu = *reinterpret_cast<uint32_t*>(&l);
}
__device__ __forceinline__ uint32_t packH2(float x, float y) {
    __half2 h;
    h.x = __float2half_rn(x);
    h.y = __float2half_rn(y);
    return *reinterpret_cast<uint32_t*>(&h);
}

// ---------------------------------------------------------------------------
// X -> fp16 single
// ---------------------------------------------------------------------------
__global__ __launch_bounds__(256) void xhalf_kernel(const float* __restrict__ x)
{
    int i = (blockIdx.x * 256 + threadIdx.x) * 4;
    float4 v = *(const float4*)(x + i);
    *(uint2*)(g_Xh + i) = make_uint2(packH2(v.x, v.y), packH2(v.z, v.w));
}

// ---------------------------------------------------------------------------
// W transpose + fp16 split: W [k][n] fp32 -> Wt hi/lo [n][k]
// ---------------------------------------------------------------------------
__global__ __launch_bounds__(256) void wtrans_kernel(
    const float* __restrict__ Wq, const float* __restrict__ Wk, const float* __restrict__ Wv)
{
    __shared__ float t[32][33];
    const float* W = (blockIdx.z == 0) ? Wq : (blockIdx.z == 1) ? Wk : Wv;
    const size_t zoff = (size_t)blockIdx.z * DM * DM;
    const int n0 = blockIdx.x * 32, k0 = blockIdx.y * 32;
    const int tx = threadIdx.x, ty = threadIdx.y;  // (32, 8)

#pragma unroll
    for (int j = 0; j < 32; j += 8)
        t[ty + j][tx] = W[(size_t)(k0 + ty + j) * DM + n0 + tx];
    __syncthreads();
#pragma unroll
    for (int j = 0; j < 32; j += 8) {
        float v = t[tx][ty + j];
        __half h, l; splitH1(v, h, l);
        size_t o = zoff + (size_t)(n0 + ty + j) * DM + k0 + tx;
        g_Wth[o] = h; g_Wtl[o] = l;
    }
}

// ---------------------------------------------------------------------------
// Unified 2-pass fp16 mma.sync GEMM: acc += Ah*Bh + Ah*Bl.
// 128x128 CTA tile, 8 warps of 32x64, BK=32, cp.async double-buffered,
// 2 CTAs/SM (128-reg cap).
//  MODE 0: proj (z=blockIdx.z+zbase: 0=Q,1=K,2=V). A=Xh, B=Wt[z] hi/lo.
//          z==0 -> Q single fp16; z==1 -> K hi/lo; z==2 -> V hi/lo.
//  MODE 3: scores. A=Q single, B=K hi/lo. tri grid; out g_S fp32 (scaled+masked).
//  MODE 4: PV split-K. A=P single, B=V hi/lo [k][n] (trans ldmatrix).
//          atomicAdd accumulation into zeroed Oext.
// ---------------------------------------------------------------------------
template<int MODE>
__global__ __launch_bounds__(NTHREADS, 2) void hgemm(float* __restrict__ Oext, int zbase)
{
    extern __shared__ char smem[];
    const uint32_t sb = smem_u32(smem);
    const int tid  = threadIdx.x;
    const int wid  = tid >> 5;
    const int lane = tid & 31;
    const int wr   = wid & 3;        // warp row (32 rows)
    const int wc   = wid >> 2;       // warp col (64 cols)

    int m0, n0, br = 0, bc = 0;
    int cbeg = 0, cend = 0;
    if (MODE == 3) {
        int i = (int)blockIdx.x;
        br = (int)((sqrtf(8.0f * (float)i + 1.0f) - 1.0f) * 0.5f);
        while ((br + 1) * (br + 2) / 2 <= i) br++;
        while (br * (br + 1) / 2 > i)        br--;
        bc = i - br * (br + 1) / 2;
        m0 = br * TM; n0 = bc * TN;
        cbeg = 0; cend = DM / BK;
    } else if (MODE == 4) {
        // segment decode: S(i) = floor((i+1)^2/4) cumulative segs per column-slice
        const int idx = (int)blockIdx.x;
        const int q = idx >> 3;
        int i = (int)(2.0f * sqrtf((float)q));
        if (i > 31) i = 31;
        if (i < 0)  i = 0;
        while (i < 31 && ((i + 2) * (i + 2)) / 4 <= q) i++;
        while (i > 0  && ((i + 1) * (i + 1)) / 4 > q)  i--;
        const int u   = idx - 8 * (((i + 1) * (i + 1)) / 4);
        const int seg = u >> 3;
        const int j   = u & 7;
        m0 = i * TM; n0 = j * TN;
        cbeg = seg * SEGCH;
        const int nch_tot = 4 * (i + 1);
        cend = (cbeg + SEGCH < nch_tot) ? (cbeg + SEGCH) : nch_tot;
    } else {
        m0 = blockIdx.y * TM; n0 = blockIdx.x * TN;
        cbeg = 0; cend = DM / BK;
    }

    const __half *Aa, *Bh, *Bl;
    int lda, ldb;
    int z = 0;
    if (MODE == 0) {
        z = (int)blockIdx.z + zbase;
        Aa = g_Xh; lda = DM; ldb = DM;
        Bh = g_Wth + (size_t)z * DM * DM;
        Bl = g_Wtl + (size_t)z * DM * DM;
    } else if (MODE == 3) {
        Aa = g_Q; lda = DM; ldb = DM;
        Bh = g_Kh; Bl = g_Kl;
    } else {
        Aa = g_P; lda = SEQ; ldb = DM;
        Bh = g_Vh; Bl = g_Vl;   // [k][n], n contiguous
    }

    float acc[2][8][4];
#pragma unroll
    for (int mi = 0; mi < 2; mi++)
#pragma unroll
        for (int nf = 0; nf < 8; nf++)
#pragma unroll
            for (int q2 = 0; q2 < 4; q2++) acc[mi][nf][q2] = 0.0f;

    // ---- chunk loader
    auto load_chunk = [&](int c) {
        const int k0  = c * BK;
        const uint32_t base = sb + (uint32_t)(c & 1) * BUFB;
        // A: 128 rows x 32 fp16 (64B/row, 4 chunks)
        for (int u2 = tid; u2 < 512; u2 += NTHREADS) {
            int row = u2 >> 2, ch = u2 & 3;
            size_t go = (size_t)(m0 + row) * lda + k0 + ch * 8;
            CP16(base + row * A_PITCH + ch * 16, Aa + go);
        }
        if (MODE == 4) {
            // B: 32 k-rows x 128 n, XOR-swizzled chunks
            for (int u2 = tid; u2 < 512; u2 += NTHREADS) {
                int k = u2 >> 4, ch = u2 & 15;
                size_t go = (size_t)(k0 + k) * ldb + n0 + ch * 8;
                uint32_t db = base + BHI_OFF + k * 256 + ((ch ^ (k & 7)) << 4);
                CP16(db,                       Bh + go);
                CP16(db + (BLO_OFF - BHI_OFF), Bl + go);
            }
        } else {
            // B: 128 n-rows x 32 k (K-major, 80B pitch)
            for (int u2 = tid; u2 < 512; u2 += NTHREADS) {
                int row = u2 >> 2, ch = u2 & 3;
                size_t gb = (size_t)(n0 + row) * ldb + k0 + ch * 8;
                uint32_t db = base + BHI_OFF + row * A_PITCH + ch * 16;
                CP16(db,                       Bh + gb);
                CP16(db + (BLO_OFF - BHI_OFF), Bl + gb);
            }
        }
    };

    load_chunk(cbeg);
    CP_COMMIT();

    for (int c = cbeg; c < cend; c++) {
        if (c + 1 < cend) { load_chunk(c + 1); CP_COMMIT(); CP_WAIT(1); }
        else              { CP_WAIT(0); }
        __syncthreads();

        const uint32_t base = sb + (uint32_t)(c & 1) * BUFB;
#pragma unroll
        for (int ks = 0; ks < 2; ks++) {
            uint32_t ah[2][4];
#pragma unroll
            for (int mi = 0; mi < 2; mi++) {
                uint32_t aaddr = base
                    + (wr * 32 + mi * 16 + (lane & 15)) * A_PITCH
                    + (ks * 2 + (lane >> 4)) * 16;
                LDSM_X4(ah[mi], aaddr);
            }
            // B fragments: two n-tiles per ldmatrix.x4
#pragma unroll
            for (int nfp = 0; nfp < 4; nfp++) {
                uint32_t bh[4], bl[4];
                if (MODE == 4) {
                    int klo    = ks * 16 + (lane & 15);
                    int cchunk = wc * 8 + nfp * 2 + ((lane >> 4) & 1);
                    uint32_t baddr = base + BHI_OFF + klo * 256
                        + ((cchunk ^ (klo & 7)) << 4);
                    LDSM_X4T(bh, baddr);
                    LDSM_X4T(bl, baddr + (BLO_OFF - BHI_OFF));
                } else {
                    uint32_t baddr = base + BHI_OFF
                        + (wc * 64 + nfp * 16 + (lane & 7) + ((lane >> 4) & 1) * 8) * A_PITCH
                        + ks * 32 + ((lane >> 3) & 1) * 16;
                    LDSM_X4(bh, baddr);
                    LDSM_X4(bl, baddr + (BLO_OFF - BHI_OFF));
                }
#pragma unroll
                for (int mi = 0; mi < 2; mi++) {
                    MMA_F16(acc[mi][nfp * 2],     ah[mi], bh[0], bh[1]);
                    MMA_F16(acc[mi][nfp * 2],     ah[mi], bl[0], bl[1]);
                    MMA_F16(acc[mi][nfp * 2 + 1], ah[mi], bh[2], bh[3]);
                    MMA_F16(acc[mi][nfp * 2 + 1], ah[mi], bl[2], bl[3]);
                }
            }
        }
        __syncthreads();
    }

    // ---- epilogue
    const int rb = m0 + wr * 32 + (lane >> 2);
    const int cb = n0 + wc * 64 + 2 * (lane & 3);
    const float scale = 0.03125f;   // 1/sqrt(1024), MODE 3 only

#pragma unroll
    for (int mi = 0; mi < 2; mi++) {
#pragma unroll
        for (int nf = 0; nf < 8; nf++) {
            int r0 = rb + mi * 16;
            int cc = cb + nf * 8;
            float v00 = acc[mi][nf][0], v01 = acc[mi][nf][1];
            float v10 = acc[mi][nf][2], v11 = acc[mi][nf][3];
            if (MODE == 0) {
                if (z == 0) {
                    *(uint32_t*)(g_Q + (size_t)r0 * DM + cc)       = packH2(v00, v01);
                    *(uint32_t*)(g_Q + (size_t)(r0 + 8) * DM + cc) = packH2(v10, v11);
                } else {
                    __half* Oh = (z == 1) ? g_Kh : g_Vh;
                    __half* Ol = (z == 1) ? g_Kl : g_Vl;
                    uint32_t h, l;
                    splitH2(v00, v01, h, l);
                    *(uint32_t*)(Oh + (size_t)r0 * DM + cc) = h;
                    *(uint32_t*)(Ol + (size_t)r0 * DM + cc) = l;
                    splitH2(v10, v11, h, l);
                    *(uint32_t*)(Oh + (size_t)(r0 + 8) * DM + cc) = h;
                    *(uint32_t*)(Ol + (size_t)(r0 + 8) * DM + cc) = l;
                }
            } else if (MODE == 3) {
                if (br == bc) {
                    float* s0 = g_S + (size_t)r0 * SEQ + cc;
                    s0[0] = (cc + 0 <= r0) ? v00 * scale : -INFINITY;
                    s0[1] = (cc + 1 <= r0) ? v01 * scale : -INFINITY;
                    float* s1 = g_S + (size_t)(r0 + 8) * SEQ + cc;
                    s1[0] = (cc + 0 <= r0 + 8) ? v10 * scale : -INFINITY;
                    s1[1] = (cc + 1 <= r0 + 8) ? v11 * scale : -INFINITY;
                } else {
                    *(float2*)(g_S + (size_t)r0 * SEQ + cc)       = make_float2(v00 * scale, v01 * scale);
                    *(float2*)(g_S + (size_t)(r0 + 8) * SEQ + cc) = make_float2(v10 * scale, v11 * scale);
                }
            } else {
                float* p0 = Oext + (size_t)r0 * DM + cc;
                float* p1 = Oext + (size_t)(r0 + 8) * DM + cc;
                atomicAdd(p0,     v00);
                atomicAdd(p0 + 1, v01);
                atomicAdd(p1,     v10);
                atomicAdd(p1 + 1, v11);
            }
        }
    }
}

// ---------------------------------------------------------------------------
// Row softmax over g_S; emits P fp16. Row r covers [0, roundup128(r+1)).
// ---------------------------------------------------------------------------
__global__ __launch_bounds__(256) void softmax_kernel()
{
    const int r   = (int)blockIdx.x;
    const int L   = (((r >> 7) + 1) << 7);
    const float* row = g_S + (size_t)r * SEQ;
    const int tid = threadIdx.x;
    __shared__ float red[256];

    float v[16];
    int   cnt = 0;
    float mx  = -INFINITY;
    for (int c = tid; c < L; c += 256) {
        float t = row[c];
        v[cnt++] = t;
        mx = fmaxf(mx, t);
    }
    red[tid] = mx;
    __syncthreads();
#pragma unroll
    for (int s = 128; s > 0; s >>= 1) {
        if (tid < s) red[tid] = fmaxf(red[tid], red[tid + s]);
        __syncthreads();
    }
    mx = red[0];
    __syncthreads();

    float sum = 0.0f;
    for (int j = 0; j < cnt; j++) {
        v[j] = expf(v[j] - mx);
        sum += v[j];
    }
    red[tid] = sum;
    __syncthreads();
#pragma unroll
    for (int s = 128; s > 0; s >>= 1) {
        if (tid < s) red[tid] += red[tid + s];
        __syncthreads();
    }
    const float rinv = 1.0f / red[0];

    cnt = 0;
    for (int c = tid; c < L; c += 256) {
        float p = v[cnt++] * rinv;
        g_P[(size_t)r * SEQ + c] = __float2half_rn(p);
    }
}

// ---------------------------------------------------------------------------
extern "C" void kernel_launch(void* const* d_in, const int* in_sizes, int n_in,
                              void* d_out, int out_size)
{
    const float* x  = (const float*)d_in[0];
    const float* Wq = (const float*)d_in[1];
    const float* Wk = (const float*)d_in[2];
    const float* Wv = (const float*)d_in[3];
    float* out = (float*)d_out;
    (void)in_sizes; (void)n_in;

    cudaFuncSetAttribute(hgemm<0>, cudaFuncAttributeMaxDynamicSharedMemorySize, SMEM_BYTES);
    cudaFuncSetAttribute(hgemm<3>, cudaFuncAttributeMaxDynamicSharedMemorySize, SMEM_BYTES);
    cudaFuncSetAttribute(hgemm<4>, cudaFuncAttributeMaxDynamicSharedMemorySize, SMEM_BYTES);

    // side stream + fork/join events
    cudaStream_t s2;
    cudaStreamCreate(&s2);
    cudaEvent_t eFork, eJoin;
    cudaEventCreateWithFlags(&eFork, cudaEventDisableTiming);
    cudaEventCreateWithFlags(&eJoin, cudaEventDisableTiming);

    // 0) operand prep (main stream) + zero output for PV atomics
    xhalf_kernel<<<SEQ * DM / (256 * 4), 256>>>(x);
    wtrans_kernel<<<dim3(DM / 32, DM / 32, 3), dim3(32, 8)>>>(Wq, Wk, Wv);
    cudaMemsetAsync(out, 0, (size_t)out_size * sizeof(float), 0);

    // fork: V projection on side stream, overlapped with Q,K proj + scores
    cudaEventRecord(eFork, 0);
    cudaStreamWaitEvent(s2, eFork, 0);
    hgemm<0><<<dim3(DM / TN, SEQ / TM, 1), NTHREADS, SMEM_BYTES, s2>>>(nullptr, 2);  // V
    cudaEventRecord(eJoin, s2);

    // 1) Q,K projections (main stream)
    hgemm<0><<<dim3(DM / TN, SEQ / TM, 2), NTHREADS, SMEM_BYTES>>>(nullptr, 0);

    // 2) causal scores (lower-triangular blocks only)
    const int nTri = (SEQ / TM) * (SEQ / TM + 1) / 2;   // 528
    hgemm<3><<<nTri, NTHREADS, SMEM_BYTES>>>(nullptr, 0);

    // 3) softmax -> P fp16
    softmax_kernel<<<SEQ, 256>>>();

    // join: PV needs V
    cudaStreamWaitEvent(0, eJoin, 0);

    // 4) O = P @ V, split-K segments (2176 CTAs)
    const int nSeg = 8 * ((33 * 33) / 4);   // 2176
    hgemm<4><<<nSeg, NTHREADS, SMEM_BYTES>>>(out, 0);
}

// round 13
// speedup vs baseline: 2.1973x; 1.2448x over previous
#include <cuda_runtime.h>
#include <cuda_bf16.h>
#include <cuda_fp16.h>
#include <math.h>
#include <stdint.h>

#define SEQ 4096
#define DM  1024
#define TM  128
#define TN  128
#define BK  32

#define NTHREADS 256

// PV split-K: 8 chunks (= 256 k-elements) per segment
#define SEGCH 8

// smem per stage: A(single fp16)[128*80B]  Bhi  Blo(MODE 0 only)
#define A_PITCH  80        // 64B data + 16B pad -> conflict-free ldmatrix
#define BHI_OFF  10240
#define BLO_OFF  20480
#define BUFB     30720
#define SMEM_BYTES (2 * BUFB)

// ---------------- scratch (device globals; allocation-free) ----------------
__device__ __half  g_Xh [SEQ * DM];                        // X single fp16
__device__ __half  g_Q  [SEQ * DM];                        // Q single fp16
__device__ __half  g_K  [SEQ * DM];                        // K single fp16
__device__ __half  g_V  [SEQ * DM];                        // V single fp16
__device__ __half  g_Wth[3 * DM * DM], g_Wtl[3 * DM * DM]; // W^T [n][k] hi/lo fp16
__device__ __half  g_P  [(size_t)SEQ * SEQ];               // softmax out fp16
__device__ float   g_S  [(size_t)SEQ * SEQ];

// ---------------- PTX helpers (baseline PTX only) ----------------
__device__ __forceinline__ uint32_t smem_u32(const void* p) {
    uint32_t a;
    asm("{ .reg .u64 t; cvta.to.shared.u64 t, %1; cvt.u32.u64 %0, t; }" : "=r"(a) : "l"(p));
    return a;
}

#define CP16(dst, src) \
    asm volatile("cp.async.cg.shared.global [%0], [%1], 16;" :: "r"(dst), "l"(src) : "memory")
#define CP_COMMIT() asm volatile("cp.async.commit_group;" ::: "memory")
#define CP_WAIT(n)  asm volatile("cp.async.wait_group %0;" :: "n"(n) : "memory")

#define LDSM_X4(r, addr) \
    asm volatile("ldmatrix.sync.aligned.m8n8.x4.shared.b16 {%0,%1,%2,%3}, [%4];" \
        : "=r"((r)[0]), "=r"((r)[1]), "=r"((r)[2]), "=r"((r)[3]) : "r"(addr))
#define LDSM_X4T(r, addr) \
    asm volatile("ldmatrix.sync.aligned.m8n8.x4.trans.shared.b16 {%0,%1,%2,%3}, [%4];" \
        : "=r"((r)[0]), "=r"((r)[1]), "=r"((r)[2]), "=r"((r)[3]) : "r"(addr))

#define MMA_F16(d, a, b0, b1) \
    asm volatile("mma.sync.aligned.m16n8k16.row.col.f32.f16.f16.f32 " \
        "{%0,%1,%2,%3}, {%4,%5,%6,%7}, {%8,%9}, {%0,%1,%2,%3};" \
        : "+f"((d)[0]), "+f"((d)[1]), "+f"((d)[2]), "+f"((d)[3]) \
        : "r"((a)[0]), "r"((a)[1]), "r"((a)[2]), "r"((a)[3]), "r"(b0), "r"(b1))

// ---------------- fp16 split/pack helpers ----------------
__device__ __forceinline__ void splitH1(float v, __half& h, __half& l) {
    h = __float2half_rn(v);
    l = __float2half_rn(v - __half2float(h));
}
__device__ __forceinline__ uint32_t packH2(float x, float y) {
    __half2 h;
    h.x = __float2half_rn(x);
    h.y = __float2half_rn(y);
    return *reinterpret_cast<uint32_t*>(&h);
}

// ---------------------------------------------------------------------------
// X -> fp16 single
// ---------------------------------------------------------------------------
__global__ __launch_bounds__(256) void xhalf_kernel(const float* __restrict__ x)
{
    int i = (blockIdx.x * 256 + threadIdx.x) * 4;
    float4 v = *(const float4*)(x + i);
    *(uint2*)(g_Xh + i) = make_uint2(packH2(v.x, v.y), packH2(v.z, v.w));
}

// ---------------------------------------------------------------------------
// W transpose + fp16 split: W [k][n] fp32 -> Wt hi/lo [n][k]
// ---------------------------------------------------------------------------
__global__ __launch_bounds__(256) void wtrans_kernel(
    const float* __restrict__ Wq, const float* __restrict__ Wk, const float* __restrict__ Wv)
{
    __shared__ float t[32][33];
    const float* W = (blockIdx.z == 0) ? Wq : (blockIdx.z == 1) ? Wk : Wv;
    const size_t zoff = (size_t)blockIdx.z * DM * DM;
    const int n0 = blockIdx.x * 32, k0 = blockIdx.y * 32;
    const int tx = threadIdx.x, ty = threadIdx.y;  // (32, 8)

#pragma unroll
    for (int j = 0; j < 32; j += 8)
        t[ty + j][tx] = W[(size_t)(k0 + ty + j) * DM + n0 + tx];
    __syncthreads();
#pragma unroll
    for (int j = 0; j < 32; j += 8) {
        float v = t[tx][ty + j];
        __half h, l; splitH1(v, h, l);
        size_t o = zoff + (size_t)(n0 + ty + j) * DM + k0 + tx;
        g_Wth[o] = h; g_Wtl[o] = l;
    }
}

// ---------------------------------------------------------------------------
// Unified fp16 mma.sync GEMM. 128x128 CTA tile, 8 warps of 32x64, BK=32,
// cp.async double-buffered, 2 CTAs/SM (128-reg cap).
//  MODE 0: proj (z=blockIdx.z+zbase: 0=Q,1=K,2=V). 2-pass: A=Xh, B=Wt hi/lo.
//          Outputs single fp16 (Q/K/V).
//  MODE 3: scores. 1-pass: A=Q, B=K single. tri grid; g_S fp32 scaled+masked.
//  MODE 4: PV split-K. 1-pass: A=P, B=V single [k][n] (trans ldmatrix).
//          atomicAdd accumulation into zeroed Oext.
// ---------------------------------------------------------------------------
template<int MODE>
__global__ __launch_bounds__(NTHREADS, 2) void hgemm(float* __restrict__ Oext, int zbase)
{
    extern __shared__ char smem[];
    const uint32_t sb = smem_u32(smem);
    const int tid  = threadIdx.x;
    const int wid  = tid >> 5;
    const int lane = tid & 31;
    const int wr   = wid & 3;        // warp row (32 rows)
    const int wc   = wid >> 2;       // warp col (64 cols)

    int m0, n0, br = 0, bc = 0;
    int cbeg = 0, cend = 0;
    if (MODE == 3) {
        int i = (int)blockIdx.x;
        br = (int)((sqrtf(8.0f * (float)i + 1.0f) - 1.0f) * 0.5f);
        while ((br + 1) * (br + 2) / 2 <= i) br++;
        while (br * (br + 1) / 2 > i)        br--;
        bc = i - br * (br + 1) / 2;
        m0 = br * TM; n0 = bc * TN;
        cbeg = 0; cend = DM / BK;
    } else if (MODE == 4) {
        // segment decode: S(i) = floor((i+1)^2/4) cumulative segs per column-slice
        const int idx = (int)blockIdx.x;
        const int q = idx >> 3;
        int i = (int)(2.0f * sqrtf((float)q));
        if (i > 31) i = 31;
        if (i < 0)  i = 0;
        while (i < 31 && ((i + 2) * (i + 2)) / 4 <= q) i++;
        while (i > 0  && ((i + 1) * (i + 1)) / 4 > q)  i--;
        const int u   = idx - 8 * (((i + 1) * (i + 1)) / 4);
        const int seg = u >> 3;
        const int j   = u & 7;
        m0 = i * TM; n0 = j * TN;
        cbeg = seg * SEGCH;
        const int nch_tot = 4 * (i + 1);
        cend = (cbeg + SEGCH < nch_tot) ? (cbeg + SEGCH) : nch_tot;
    } else {
        m0 = blockIdx.y * TM; n0 = blockIdx.x * TN;
        cbeg = 0; cend = DM / BK;
    }

    const __half *Aa, *Bh, *Bl = nullptr;
    int lda, ldb;
    int z = 0;
    if (MODE == 0) {
        z = (int)blockIdx.z + zbase;
        Aa = g_Xh; lda = DM; ldb = DM;
        Bh = g_Wth + (size_t)z * DM * DM;
        Bl = g_Wtl + (size_t)z * DM * DM;
    } else if (MODE == 3) {
        Aa = g_Q; lda = DM; ldb = DM;
        Bh = g_K;
    } else {
        Aa = g_P; lda = SEQ; ldb = DM;
        Bh = g_V;   // [k][n], n contiguous
    }

    float acc[2][8][4];
#pragma unroll
    for (int mi = 0; mi < 2; mi++)
#pragma unroll
        for (int nf = 0; nf < 8; nf++)
#pragma unroll
            for (int q2 = 0; q2 < 4; q2++) acc[mi][nf][q2] = 0.0f;

    // ---- chunk loader
    auto load_chunk = [&](int c) {
        const int k0  = c * BK;
        const uint32_t base = sb + (uint32_t)(c & 1) * BUFB;
        // A: 128 rows x 32 fp16 (64B/row, 4 chunks)
        for (int u2 = tid; u2 < 512; u2 += NTHREADS) {
            int row = u2 >> 2, ch = u2 & 3;
            size_t go = (size_t)(m0 + row) * lda + k0 + ch * 8;
            CP16(base + row * A_PITCH + ch * 16, Aa + go);
        }
        if (MODE == 4) {
            // B: 32 k-rows x 128 n, XOR-swizzled chunks (single)
            for (int u2 = tid; u2 < 512; u2 += NTHREADS) {
                int k = u2 >> 4, ch = u2 & 15;
                size_t go = (size_t)(k0 + k) * ldb + n0 + ch * 8;
                uint32_t db = base + BHI_OFF + k * 256 + ((ch ^ (k & 7)) << 4);
                CP16(db, Bh + go);
            }
        } else {
            // B: 128 n-rows x 32 k (K-major, 80B pitch)
            for (int u2 = tid; u2 < 512; u2 += NTHREADS) {
                int row = u2 >> 2, ch = u2 & 3;
                size_t gb = (size_t)(n0 + row) * ldb + k0 + ch * 8;
                uint32_t db = base + BHI_OFF + row * A_PITCH + ch * 16;
                CP16(db, Bh + gb);
                if (MODE == 0)
                    CP16(db + (BLO_OFF - BHI_OFF), Bl + gb);
            }
        }
    };

    load_chunk(cbeg);
    CP_COMMIT();

    for (int c = cbeg; c < cend; c++) {
        if (c + 1 < cend) { load_chunk(c + 1); CP_COMMIT(); CP_WAIT(1); }
        else              { CP_WAIT(0); }
        __syncthreads();

        const uint32_t base = sb + (uint32_t)(c & 1) * BUFB;
#pragma unroll
        for (int ks = 0; ks < 2; ks++) {
            uint32_t ah[2][4];
#pragma unroll
            for (int mi = 0; mi < 2; mi++) {
                uint32_t aaddr = base
                    + (wr * 32 + mi * 16 + (lane & 15)) * A_PITCH
                    + (ks * 2 + (lane >> 4)) * 16;
                LDSM_X4(ah[mi], aaddr);
            }
            // B fragments: two n-tiles per ldmatrix.x4
#pragma unroll
            for (int nfp = 0; nfp < 4; nfp++) {
                uint32_t bh[4], bl[4];
                if (MODE == 4) {
                    int klo    = ks * 16 + (lane & 15);
                    int cchunk = wc * 8 + nfp * 2 + ((lane >> 4) & 1);
                    uint32_t baddr = base + BHI_OFF + klo * 256
                        + ((cchunk ^ (klo & 7)) << 4);
                    LDSM_X4T(bh, baddr);
                } else {
                    uint32_t baddr = base + BHI_OFF
                        + (wc * 64 + nfp * 16 + (lane & 7) + ((lane >> 4) & 1) * 8) * A_PITCH
                        + ks * 32 + ((lane >> 3) & 1) * 16;
                    LDSM_X4(bh, baddr);
                    if (MODE == 0)
                        LDSM_X4(bl, baddr + (BLO_OFF - BHI_OFF));
                }
#pragma unroll
                for (int mi = 0; mi < 2; mi++) {
                    MMA_F16(acc[mi][nfp * 2],     ah[mi], bh[0], bh[1]);
                    MMA_F16(acc[mi][nfp * 2 + 1], ah[mi], bh[2], bh[3]);
                    if (MODE == 0) {
                        MMA_F16(acc[mi][nfp * 2],     ah[mi], bl[0], bl[1]);
                        MMA_F16(acc[mi][nfp * 2 + 1], ah[mi], bl[2], bl[3]);
                    }
                }
            }
        }
        __syncthreads();
    }

    // ---- epilogue
    const int rb = m0 + wr * 32 + (lane >> 2);
    const int cb = n0 + wc * 64 + 2 * (lane & 3);
    const float scale = 0.03125f;   // 1/sqrt(1024), MODE 3 only

#pragma unroll
    for (int mi = 0; mi < 2; mi++) {
#pragma unroll
        for (int nf = 0; nf < 8; nf++) {
            int r0 = rb + mi * 16;
            int cc = cb + nf * 8;
            float v00 = acc[mi][nf][0], v01 = acc[mi][nf][1];
            float v10 = acc[mi][nf][2], v11 = acc[mi][nf][3];
            if (MODE == 0) {
                __half* Oq = (z == 0) ? g_Q : (z == 1) ? g_K : g_V;
                *(uint32_t*)(Oq + (size_t)r0 * DM + cc)       = packH2(v00, v01);
                *(uint32_t*)(Oq + (size_t)(r0 + 8) * DM + cc) = packH2(v10, v11);
            } else if (MODE == 3) {
                if (br == bc) {
                    float* s0 = g_S + (size_t)r0 * SEQ + cc;
                    s0[0] = (cc + 0 <= r0) ? v00 * scale : -INFINITY;
                    s0[1] = (cc + 1 <= r0) ? v01 * scale : -INFINITY;
                    float* s1 = g_S + (size_t)(r0 + 8) * SEQ + cc;
                    s1[0] = (cc + 0 <= r0 + 8) ? v10 * scale : -INFINITY;
                    s1[1] = (cc + 1 <= r0 + 8) ? v11 * scale : -INFINITY;
                } else {
                    *(float2*)(g_S + (size_t)r0 * SEQ + cc)       = make_float2(v00 * scale, v01 * scale);
                    *(float2*)(g_S + (size_t)(r0 + 8) * SEQ + cc) = make_float2(v10 * scale, v11 * scale);
                }
            } else {
                float* p0 = Oext + (size_t)r0 * DM + cc;
                float* p1 = Oext + (size_t)(r0 + 8) * DM + cc;
                atomicAdd(p0,     v00);
                atomicAdd(p0 + 1, v01);
                atomicAdd(p1,     v10);
                atomicAdd(p1 + 1, v11);
            }
        }
    }
}

// ---------------------------------------------------------------------------
// Row softmax over g_S; emits P fp16. Row r covers [0, roundup128(r+1)).
// ---------------------------------------------------------------------------
__global__ __launch_bounds__(256) void softmax_kernel()
{
    const int r   = (int)blockIdx.x;
    const int L   = (((r >> 7) + 1) << 7);
    const float* row = g_S + (size_t)r * SEQ;
    const int tid = threadIdx.x;
    __shared__ float red[256];

    float v[16];
    int   cnt = 0;
    float mx  = -INFINITY;
    for (int c = tid; c < L; c += 256) {
        float t = row[c];
        v[cnt++] = t;
        mx = fmaxf(mx, t);
    }
    red[tid] = mx;
    __syncthreads();
#pragma unroll
    for (int s = 128; s > 0; s >>= 1) {
        if (tid < s) red[tid] = fmaxf(red[tid], red[tid + s]);
        __syncthreads();
    }
    mx = red[0];
    __syncthreads();

    float sum = 0.0f;
    for (int j = 0; j < cnt; j++) {
        v[j] = __expf(v[j] - mx);
        sum += v[j];
    }
    red[tid] = sum;
    __syncthreads();
#pragma unroll
    for (int s = 128; s > 0; s >>= 1) {
        if (tid < s) red[tid] += red[tid + s];
        __syncthreads();
    }
    const float rinv = 1.0f / red[0];

    cnt = 0;
    for (int c = tid; c < L; c += 256) {
        float p = v[cnt++] * rinv;
        g_P[(size_t)r * SEQ + c] = __float2half_rn(p);
    }
}

// ---------------------------------------------------------------------------
extern "C" void kernel_launch(void* const* d_in, const int* in_sizes, int n_in,
                              void* d_out, int out_size)
{
    const float* x  = (const float*)d_in[0];
    const float* Wq = (const float*)d_in[1];
    const float* Wk = (const float*)d_in[2];
    const float* Wv = (const float*)d_in[3];
    float* out = (float*)d_out;
    (void)in_sizes; (void)n_in;

    cudaFuncSetAttribute(hgemm<0>, cudaFuncAttributeMaxDynamicSharedMemorySize, SMEM_BYTES);
    cudaFuncSetAttribute(hgemm<3>, cudaFuncAttributeMaxDynamicSharedMemorySize, SMEM_BYTES);
    cudaFuncSetAttribute(hgemm<4>, cudaFuncAttributeMaxDynamicSharedMemorySize, SMEM_BYTES);

    // side stream + fork/join events
    cudaStream_t s2;
    cudaStreamCreate(&s2);
    cudaEvent_t eFork, eJoin;
    cudaEventCreateWithFlags(&eFork, cudaEventDisableTiming);
    cudaEventCreateWithFlags(&eJoin, cudaEventDisableTiming);

    // 0) operand prep (main stream) + zero output for PV atomics
    xhalf_kernel<<<SEQ * DM / (256 * 4), 256>>>(x);
    wtrans_kernel<<<dim3(DM / 32, DM / 32, 3), dim3(32, 8)>>>(Wq, Wk, Wv);
    cudaMemsetAsync(out, 0, (size_t)out_size * sizeof(float), 0);

    // fork: V projection on side stream, overlapped with Q,K proj + scores
    cudaEventRecord(eFork, 0);
    cudaStreamWaitEvent(s2, eFork, 0);
    hgemm<0><<<dim3(DM / TN, SEQ / TM, 1), NTHREADS, SMEM_BYTES, s2>>>(nullptr, 2);  // V
    cudaEventRecord(eJoin, s2);

    // 1) Q,K projections (main stream)
    hgemm<0><<<dim3(DM / TN, SEQ / TM, 2), NTHREADS, SMEM_BYTES>>>(nullptr, 0);

    // 2) causal scores (lower-triangular blocks only, single-pass fp16)
    const int nTri = (SEQ / TM) * (SEQ / TM + 1) / 2;   // 528
    hgemm<3><<<nTri, NTHREADS, SMEM_BYTES>>>(nullptr, 0);

    // 3) softmax -> P fp16
    softmax_kernel<<<SEQ, 256>>>();

    // join: PV needs V
    cudaStreamWaitEvent(0, eJoin, 0);

    // 4) O = P @ V, split-K segments (2176 CTAs, single-pass fp16)
    const int nSeg = 8 * ((33 * 33) / 4);   // 2176
    hgemm<4><<<nSeg, NTHREADS, SMEM_BYTES>>>(out, 0);
}

// round 14
// speedup vs baseline: 2.7736x; 1.2622x over previous
#include <cuda_runtime.h>
#include <cuda_bf16.h>
#include <cuda_fp16.h>
#include <math.h>
#include <stdint.h>

#define SEQ 4096
#define DM  1024
#define TM  128
#define TN  128
#define BK  32

#define NTHREADS 256

// PV split-K: 8 chunks (= 256 k-elements) per segment
#define SEGCH 8

// smem per stage: A[128*80B]  B[128*80B or 32*256B]
#define A_PITCH  80        // 64B data + 16B pad -> conflict-free ldmatrix
#define B_OFF    10240
#define BUFB     20480
#define NSTAGE   3
#define SMEM_BYTES (NSTAGE * BUFB)

// ---------------- scratch (device globals; allocation-free) ----------------
__device__ __half  g_Xh [SEQ * DM];                 // X single fp16
__device__ __half  g_Q  [SEQ * DM];                 // Q single fp16
__device__ __half  g_K  [SEQ * DM];                 // K single fp16
__device__ __half  g_V  [SEQ * DM];                 // V single fp16
__device__ __half  g_Wt [3 * DM * DM];              // W^T [n][k] single fp16
__device__ __half  g_P  [(size_t)SEQ * SEQ];        // softmax out fp16
__device__ float   g_S  [(size_t)SEQ * SEQ];

// ---------------- PTX helpers (baseline PTX only) ----------------
__device__ __forceinline__ uint32_t smem_u32(const void* p) {
    uint32_t a;
    asm("{ .reg .u64 t; cvta.to.shared.u64 t, %1; cvt.u32.u64 %0, t; }" : "=r"(a) : "l"(p));
    return a;
}

#define CP16(dst, src) \
    asm volatile("cp.async.cg.shared.global [%0], [%1], 16;" :: "r"(dst), "l"(src) : "memory")
#define CP_COMMIT() asm volatile("cp.async.commit_group;" ::: "memory")
#define CP_WAIT(n)  asm volatile("cp.async.wait_group %0;" :: "n"(n) : "memory")

#define LDSM_X4(r, addr) \
    asm volatile("ldmatrix.sync.aligned.m8n8.x4.shared.b16 {%0,%1,%2,%3}, [%4];" \
        : "=r"((r)[0]), "=r"((r)[1]), "=r"((r)[2]), "=r"((r)[3]) : "r"(addr))
#define LDSM_X4T(r, addr) \
    asm volatile("ldmatrix.sync.aligned.m8n8.x4.trans.shared.b16 {%0,%1,%2,%3}, [%4];" \
        : "=r"((r)[0]), "=r"((r)[1]), "=r"((r)[2]), "=r"((r)[3]) : "r"(addr))

#define MMA_F16(d, a, b0, b1) \
    asm volatile("mma.sync.aligned.m16n8k16.row.col.f32.f16.f16.f32 " \
        "{%0,%1,%2,%3}, {%4,%5,%6,%7}, {%8,%9}, {%0,%1,%2,%3};" \
        : "+f"((d)[0]), "+f"((d)[1]), "+f"((d)[2]), "+f"((d)[3]) \
        : "r"((a)[0]), "r"((a)[1]), "r"((a)[2]), "r"((a)[3]), "r"(b0), "r"(b1))

// ---------------- fp16 pack helper ----------------
__device__ __forceinline__ uint32_t packH2(float x, float y) {
    __half2 h;
    h.x = __float2half_rn(x);
    h.y = __float2half_rn(y);
    return *reinterpret_cast<uint32_t*>(&h);
}

// ---------------------------------------------------------------------------
// X -> fp16 single
// ---------------------------------------------------------------------------
__global__ __launch_bounds__(256) void xhalf_kernel(const float* __restrict__ x)
{
    int i = (blockIdx.x * 256 + threadIdx.x) * 4;
    float4 v = *(const float4*)(x + i);
    *(uint2*)(g_Xh + i) = make_uint2(packH2(v.x, v.y), packH2(v.z, v.w));
}

// ---------------------------------------------------------------------------
// W transpose: W [k][n] fp32 -> Wt [n][k] single fp16
// ---------------------------------------------------------------------------
__global__ __launch_bounds__(256) void wtrans_kernel(
    const float* __restrict__ Wq, const float* __restrict__ Wk, const float* __restrict__ Wv)
{
    __shared__ float t[32][33];
    const float* W = (blockIdx.z == 0) ? Wq : (blockIdx.z == 1) ? Wk : Wv;
    const size_t zoff = (size_t)blockIdx.z * DM * DM;
    const int n0 = blockIdx.x * 32, k0 = blockIdx.y * 32;
    const int tx = threadIdx.x, ty = threadIdx.y;  // (32, 8)

#pragma unroll
    for (int j = 0; j < 32; j += 8)
        t[ty + j][tx] = W[(size_t)(k0 + ty + j) * DM + n0 + tx];
    __syncthreads();
#pragma unroll
    for (int j = 0; j < 32; j += 8) {
        float v = t[tx][ty + j];
        g_Wt[zoff + (size_t)(n0 + ty + j) * DM + k0 + tx] = __float2half_rn(v);
    }
}

// ---------------------------------------------------------------------------
// Unified 1-pass fp16 mma.sync GEMM. 128x128 CTA tile, 8 warps of 32x64,
// BK=32, cp.async 3-stage pipeline, 2 CTAs/SM (128-reg cap).
//  MODE 0: proj (z=blockIdx.z+zbase: 0=Q,1=K,2=V). A=Xh, B=Wt[z].
//  MODE 3: scores. A=Q, B=K. tri grid; g_S fp32 scaled+masked.
//  MODE 4: PV split-K. A=P, B=V [k][n] (trans ldmatrix). atomicAdd into Oext.
// ---------------------------------------------------------------------------
template<int MODE>
__global__ __launch_bounds__(NTHREADS, 2) void hgemm(float* __restrict__ Oext, int zbase)
{
    extern __shared__ char smem[];
    const uint32_t sb = smem_u32(smem);
    const int tid  = threadIdx.x;
    const int wid  = tid >> 5;
    const int lane = tid & 31;
    const int wr   = wid & 3;        // warp row (32 rows)
    const int wc   = wid >> 2;       // warp col (64 cols)

    int m0, n0, br = 0, bc = 0;
    int cbeg = 0, cend = 0;
    if (MODE == 3) {
        int i = (int)blockIdx.x;
        br = (int)((sqrtf(8.0f * (float)i + 1.0f) - 1.0f) * 0.5f);
        while ((br + 1) * (br + 2) / 2 <= i) br++;
        while (br * (br + 1) / 2 > i)        br--;
        bc = i - br * (br + 1) / 2;
        m0 = br * TM; n0 = bc * TN;
        cbeg = 0; cend = DM / BK;
    } else if (MODE == 4) {
        // segment decode: S(i) = floor((i+1)^2/4) cumulative segs per column-slice
        const int idx = (int)blockIdx.x;
        const int q = idx >> 3;
        int i = (int)(2.0f * sqrtf((float)q));
        if (i > 31) i = 31;
        if (i < 0)  i = 0;
        while (i < 31 && ((i + 2) * (i + 2)) / 4 <= q) i++;
        while (i > 0  && ((i + 1) * (i + 1)) / 4 > q)  i--;
        const int u   = idx - 8 * (((i + 1) * (i + 1)) / 4);
        const int seg = u >> 3;
        const int j   = u & 7;
        m0 = i * TM; n0 = j * TN;
        cbeg = seg * SEGCH;
        const int nch_tot = 4 * (i + 1);
        cend = (cbeg + SEGCH < nch_tot) ? (cbeg + SEGCH) : nch_tot;
    } else {
        m0 = blockIdx.y * TM; n0 = blockIdx.x * TN;
        cbeg = 0; cend = DM / BK;
    }

    const __half *Aa, *Bb;
    int lda, ldb;
    int z = 0;
    if (MODE == 0) {
        z = (int)blockIdx.z + zbase;
        Aa = g_Xh; lda = DM; ldb = DM;
        Bb = g_Wt + (size_t)z * DM * DM;
    } else if (MODE == 3) {
        Aa = g_Q; lda = DM; ldb = DM;
        Bb = g_K;
    } else {
        Aa = g_P; lda = SEQ; ldb = DM;
        Bb = g_V;   // [k][n], n contiguous
    }

    float acc[2][8][4];
#pragma unroll
    for (int mi = 0; mi < 2; mi++)
#pragma unroll
        for (int nf = 0; nf < 8; nf++)
#pragma unroll
            for (int q2 = 0; q2 < 4; q2++) acc[mi][nf][q2] = 0.0f;

    // ---- chunk loader (stage = c % NSTAGE)
    auto load_chunk = [&](int c) {
        const int k0  = c * BK;
        const uint32_t base = sb + (uint32_t)(c % NSTAGE) * BUFB;
        // A: 128 rows x 32 fp16 (64B/row, 4 chunks)
        for (int u2 = tid; u2 < 512; u2 += NTHREADS) {
            int row = u2 >> 2, ch = u2 & 3;
            size_t go = (size_t)(m0 + row) * lda + k0 + ch * 8;
            CP16(base + row * A_PITCH + ch * 16, Aa + go);
        }
        if (MODE == 4) {
            // B: 32 k-rows x 128 n, XOR-swizzled chunks
            for (int u2 = tid; u2 < 512; u2 += NTHREADS) {
                int k = u2 >> 4, ch = u2 & 15;
                size_t go = (size_t)(k0 + k) * ldb + n0 + ch * 8;
                CP16(base + B_OFF + k * 256 + ((ch ^ (k & 7)) << 4), Bb + go);
            }
        } else {
            // B: 128 n-rows x 32 k (K-major, 80B pitch)
            for (int u2 = tid; u2 < 512; u2 += NTHREADS) {
                int row = u2 >> 2, ch = u2 & 3;
                size_t gb = (size_t)(n0 + row) * ldb + k0 + ch * 8;
                CP16(base + B_OFF + row * A_PITCH + ch * 16, Bb + gb);
            }
        }
    };

    // 3-stage prologue
    load_chunk(cbeg);
    CP_COMMIT();
    if (cbeg + 1 < cend) { load_chunk(cbeg + 1); CP_COMMIT(); }

    for (int c = cbeg; c < cend; c++) {
        if (c + 2 < cend) { load_chunk(c + 2); CP_COMMIT(); CP_WAIT(2); }
        else if (c + 1 < cend) { CP_WAIT(1); }
        else { CP_WAIT(0); }
        __syncthreads();

        const uint32_t base = sb + (uint32_t)(c % NSTAGE) * BUFB;
#pragma unroll
        for (int ks = 0; ks < 2; ks++) {
            uint32_t ah[2][4];
#pragma unroll
            for (int mi = 0; mi < 2; mi++) {
                uint32_t aaddr = base
                    + (wr * 32 + mi * 16 + (lane & 15)) * A_PITCH
                    + (ks * 2 + (lane >> 4)) * 16;
                LDSM_X4(ah[mi], aaddr);
            }
            // B fragments: two n-tiles per ldmatrix.x4
#pragma unroll
            for (int nfp = 0; nfp < 4; nfp++) {
                uint32_t bh[4];
                if (MODE == 4) {
                    int klo    = ks * 16 + (lane & 15);
                    int cchunk = wc * 8 + nfp * 2 + ((lane >> 4) & 1);
                    uint32_t baddr = base + B_OFF + klo * 256
                        + ((cchunk ^ (klo & 7)) << 4);
                    LDSM_X4T(bh, baddr);
                } else {
                    uint32_t baddr = base + B_OFF
                        + (wc * 64 + nfp * 16 + (lane & 7) + ((lane >> 4) & 1) * 8) * A_PITCH
                        + ks * 32 + ((lane >> 3) & 1) * 16;
                    LDSM_X4(bh, baddr);
                }
#pragma unroll
                for (int mi = 0; mi < 2; mi++) {
                    MMA_F16(acc[mi][nfp * 2],     ah[mi], bh[0], bh[1]);
                    MMA_F16(acc[mi][nfp * 2 + 1], ah[mi], bh[2], bh[3]);
                }
            }
        }
        __syncthreads();
    }

    // ---- epilogue
    const int rb = m0 + wr * 32 + (lane >> 2);
    const int cb = n0 + wc * 64 + 2 * (lane & 3);
    const float scale = 0.03125f;   // 1/sqrt(1024), MODE 3 only

#pragma unroll
    for (int mi = 0; mi < 2; mi++) {
#pragma unroll
        for (int nf = 0; nf < 8; nf++) {
            int r0 = rb + mi * 16;
            int cc = cb + nf * 8;
            float v00 = acc[mi][nf][0], v01 = acc[mi][nf][1];
            float v10 = acc[mi][nf][2], v11 = acc[mi][nf][3];
            if (MODE == 0) {
                __half* Oq = (z == 0) ? g_Q : (z == 1) ? g_K : g_V;
                *(uint32_t*)(Oq + (size_t)r0 * DM + cc)       = packH2(v00, v01);
                *(uint32_t*)(Oq + (size_t)(r0 + 8) * DM + cc) = packH2(v10, v11);
            } else if (MODE == 3) {
                if (br == bc) {
                    float* s0 = g_S + (size_t)r0 * SEQ + cc;
                    s0[0] = (cc + 0 <= r0) ? v00 * scale : -INFINITY;
                    s0[1] = (cc + 1 <= r0) ? v01 * scale : -INFINITY;
                    float* s1 = g_S + (size_t)(r0 + 8) * SEQ + cc;
                    s1[0] = (cc + 0 <= r0 + 8) ? v10 * scale : -INFINITY;
                    s1[1] = (cc + 1 <= r0 + 8) ? v11 * scale : -INFINITY;
                } else {
                    *(float2*)(g_S + (size_t)r0 * SEQ + cc)       = make_float2(v00 * scale, v01 * scale);
                    *(float2*)(g_S + (size_t)(r0 + 8) * SEQ + cc) = make_float2(v10 * scale, v11 * scale);
                }
            } else {
                float* p0 = Oext + (size_t)r0 * DM + cc;
                float* p1 = Oext + (size_t)(r0 + 8) * DM + cc;
                atomicAdd(p0,     v00);
                atomicAdd(p0 + 1, v01);
                atomicAdd(p1,     v10);
                atomicAdd(p1 + 1, v11);
            }
        }
    }
}

// ---------------------------------------------------------------------------
// Row softmax over g_S; emits P fp16. Row r covers [0, roundup128(r+1)).
// ---------------------------------------------------------------------------
__global__ __launch_bounds__(256) void softmax_kernel()
{
    const int r   = (int)blockIdx.x;
    const int L   = (((r >> 7) + 1) << 7);
    const float* row = g_S + (size_t)r * SEQ;
    const int tid = threadIdx.x;
    __shared__ float red[256];

    float v[16];
    int   cnt = 0;
    float mx  = -INFINITY;
    for (int c = tid; c < L; c += 256) {
        float t = row[c];
        v[cnt++] = t;
        mx = fmaxf(mx, t);
    }
    red[tid] = mx;
    __syncthreads();
#pragma unroll
    for (int s = 128; s > 0; s >>= 1) {
        if (tid < s) red[tid] = fmaxf(red[tid], red[tid + s]);
        __syncthreads();
    }
    mx = red[0];
    __syncthreads();

    float sum = 0.0f;
    for (int j = 0; j < cnt; j++) {
        v[j] = __expf(v[j] - mx);
        sum += v[j];
    }
    red[tid] = sum;
    __syncthreads();
#pragma unroll
    for (int s = 128; s > 0; s >>= 1) {
        if (tid < s) red[tid] += red[tid + s];
        __syncthreads();
    }
    const float rinv = 1.0f / red[0];

    cnt = 0;
    for (int c = tid; c < L; c += 256) {
        float p = v[cnt++] * rinv;
        g_P[(size_t)r * SEQ + c] = __float2half_rn(p);
    }
}

// ---------------------------------------------------------------------------
extern "C" void kernel_launch(void* const* d_in, const int* in_sizes, int n_in,
                              void* d_out, int out_size)
{
    const float* x  = (const float*)d_in[0];
    const float* Wq = (const float*)d_in[1];
    const float* Wk = (const float*)d_in[2];
    const float* Wv = (const float*)d_in[3];
    float* out = (float*)d_out;
    (void)in_sizes; (void)n_in;

    cudaFuncSetAttribute(hgemm<0>, cudaFuncAttributeMaxDynamicSharedMemorySize, SMEM_BYTES);
    cudaFuncSetAttribute(hgemm<3>, cudaFuncAttributeMaxDynamicSharedMemorySize, SMEM_BYTES);
    cudaFuncSetAttribute(hgemm<4>, cudaFuncAttributeMaxDynamicSharedMemorySize, SMEM_BYTES);

    // side stream + fork/join events
    cudaStream_t s2;
    cudaStreamCreate(&s2);
    cudaEvent_t eFork, eJoin;
    cudaEventCreateWithFlags(&eFork, cudaEventDisableTiming);
    cudaEventCreateWithFlags(&eJoin, cudaEventDisableTiming);

    // 0) operand prep (main stream) + zero output for PV atomics
    xhalf_kernel<<<SEQ * DM / (256 * 4), 256>>>(x);
    wtrans_kernel<<<dim3(DM / 32, DM / 32, 3), dim3(32, 8)>>>(Wq, Wk, Wv);
    cudaMemsetAsync(out, 0, (size_t)out_size * sizeof(float), 0);

    // fork: V projection on side stream, overlapped with Q,K proj + scores
    cudaEventRecord(eFork, 0);
    cudaStreamWaitEvent(s2, eFork, 0);
    hgemm<0><<<dim3(DM / TN, SEQ / TM, 1), NTHREADS, SMEM_BYTES, s2>>>(nullptr, 2);  // V
    cudaEventRecord(eJoin, s2);

    // 1) Q,K projections (main stream)
    hgemm<0><<<dim3(DM / TN, SEQ / TM, 2), NTHREADS, SMEM_BYTES>>>(nullptr, 0);

    // 2) causal scores (lower-triangular blocks only, single-pass fp16)
    const int nTri = (SEQ / TM) * (SEQ / TM + 1) / 2;   // 528
    hgemm<3><<<nTri, NTHREADS, SMEM_BYTES>>>(nullptr, 0);

    // 3) softmax -> P fp16
    softmax_kernel<<<SEQ, 256>>>();

    // join: PV needs V
    cudaStreamWaitEvent(0, eJoin, 0);

    // 4) O = P @ V, split-K segments (2176 CTAs, single-pass fp16)
    const int nSeg = 8 * ((33 * 33) / 4);   // 2176
    hgemm<4><<<nSeg, NTHREADS, SMEM_BYTES>>>(out, 0);
}

// round 15
// speedup vs baseline: 3.0707x; 1.1071x over previous
#include <cuda_runtime.h>
#include <cuda_bf16.h>
#include <cuda_fp16.h>
#include <math.h>
#include <stdint.h>

#define SEQ 4096
#define DM  1024
#define TM  128
#define TN  128
#define BK  64

#define NTHREADS 256

// PV split-K: 4 chunks (= 256 k-elements) per segment
#define SEGCH 4

// smem per stage: A[128 x 144B]  B[128 x 144B | 64 x 256B]
#define A_PITCH  144       // 128B data + 16B pad -> conflict-free ldmatrix
#define B_OFF    18432
#define BUFB     36864
#define NSTAGE   3
#define SMEM_BYTES (NSTAGE * BUFB)   // 110592 per CTA; x2 CTAs = 221 KB/SM

// ---------------- scratch (device globals; allocation-free) ----------------
__device__ __half  g_Xh [SEQ * DM];                 // X single fp16
__device__ __half  g_Q  [SEQ * DM];                 // Q single fp16 (pre-scaled by 1/32)
__device__ __half  g_K  [SEQ * DM];                 // K single fp16
__device__ __half  g_V  [SEQ * DM];                 // V single fp16
__device__ __half  g_Wt [3 * DM * DM];              // W^T [n][k] single fp16
__device__ __half  g_P  [(size_t)SEQ * SEQ];        // softmax out fp16
__device__ float   g_S  [(size_t)SEQ * SEQ];

// ---------------- PTX helpers (baseline PTX only) ----------------
__device__ __forceinline__ uint32_t smem_u32(const void* p) {
    uint32_t a;
    asm("{ .reg .u64 t; cvta.to.shared.u64 t, %1; cvt.u32.u64 %0, t; }" : "=r"(a) : "l"(p));
    return a;
}

#define CP16(dst, src) \
    asm volatile("cp.async.cg.shared.global [%0], [%1], 16;" :: "r"(dst), "l"(src) : "memory")
#define CP_COMMIT() asm volatile("cp.async.commit_group;" ::: "memory")
#define CP_WAIT(n)  asm volatile("cp.async.wait_group %0;" :: "n"(n) : "memory")

#define LDSM_X4(r, addr) \
    asm volatile("ldmatrix.sync.aligned.m8n8.x4.shared.b16 {%0,%1,%2,%3}, [%4];" \
        : "=r"((r)[0]), "=r"((r)[1]), "=r"((r)[2]), "=r"((r)[3]) : "r"(addr))
#define LDSM_X4T(r, addr) \
    asm volatile("ldmatrix.sync.aligned.m8n8.x4.trans.shared.b16 {%0,%1,%2,%3}, [%4];" \
        : "=r"((r)[0]), "=r"((r)[1]), "=r"((r)[2]), "=r"((r)[3]) : "r"(addr))

#define MMA_F16(d, a, b0, b1) \
    asm volatile("mma.sync.aligned.m16n8k16.row.col.f32.f16.f16.f32 " \
        "{%0,%1,%2,%3}, {%4,%5,%6,%7}, {%8,%9}, {%0,%1,%2,%3};" \
        : "+f"((d)[0]), "+f"((d)[1]), "+f"((d)[2]), "+f"((d)[3]) \
        : "r"((a)[0]), "r"((a)[1]), "r"((a)[2]), "r"((a)[3]), "r"(b0), "r"(b1))

// ---------------- fp16 pack helper ----------------
__device__ __forceinline__ uint32_t packH2(float x, float y) {
    __half2 h;
    h.x = __float2half_rn(x);
    h.y = __float2half_rn(y);
    return *reinterpret_cast<uint32_t*>(&h);
}

// ---------------------------------------------------------------------------
// X -> fp16 single
// ---------------------------------------------------------------------------
__global__ __launch_bounds__(256) void xhalf_kernel(const float* __restrict__ x)
{
    int i = (blockIdx.x * 256 + threadIdx.x) * 4;
    float4 v = *(const float4*)(x + i);
    *(uint2*)(g_Xh + i) = make_uint2(packH2(v.x, v.y), packH2(v.z, v.w));
}

// ---------------------------------------------------------------------------
// W transpose: W [k][n] fp32 -> Wt [n][k] single fp16
// ---------------------------------------------------------------------------
__global__ __launch_bounds__(256) void wtrans_kernel(
    const float* __restrict__ Wq, const float* __restrict__ Wk, const float* __restrict__ Wv)
{
    __shared__ float t[32][33];
    const float* W = (blockIdx.z == 0) ? Wq : (blockIdx.z == 1) ? Wk : Wv;
    const size_t zoff = (size_t)blockIdx.z * DM * DM;
    const int n0 = blockIdx.x * 32, k0 = blockIdx.y * 32;
    const int tx = threadIdx.x, ty = threadIdx.y;  // (32, 8)

#pragma unroll
    for (int j = 0; j < 32; j += 8)
        t[ty + j][tx] = W[(size_t)(k0 + ty + j) * DM + n0 + tx];
    __syncthreads();
#pragma unroll
    for (int j = 0; j < 32; j += 8) {
        float v = t[tx][ty + j];
        g_Wt[zoff + (size_t)(n0 + ty + j) * DM + k0 + tx] = __float2half_rn(v);
    }
}

// ---------------------------------------------------------------------------
// Unified 1-pass fp16 mma.sync GEMM. 128x128 CTA tile, 8 warps of 32x64,
// BK=64, cp.async 3-stage pipeline, 2 CTAs/SM (128-reg cap).
//  MODE 0: proj (z=blockIdx.z+zbase: 0=Q,1=K,2=V). A=Xh, B=Wt[z].
//          Q is written pre-scaled by 1/32.
//  MODE 3: scores. A=Q(pre-scaled), B=K. tri grid; g_S fp32 + causal mask.
//  MODE 4: PV split-K. A=P, B=V [k][n] (trans ldmatrix). atomicAdd into Oext.
// ---------------------------------------------------------------------------
template<int MODE>
__global__ __launch_bounds__(NTHREADS, 2) void hgemm(float* __restrict__ Oext, int zbase)
{
    extern __shared__ char smem[];
    const uint32_t sb = smem_u32(smem);
    const int tid  = threadIdx.x;
    const int wid  = tid >> 5;
    const int lane = tid & 31;
    const int wr   = wid & 3;        // warp row (32 rows)
    const int wc   = wid >> 2;       // warp col (64 cols)

    int m0, n0, br = 0, bc = 0;
    int cbeg = 0, cend = 0;
    if (MODE == 3) {
        int i = (int)blockIdx.x;
        br = (int)((sqrtf(8.0f * (float)i + 1.0f) - 1.0f) * 0.5f);
        while ((br + 1) * (br + 2) / 2 <= i) br++;
        while (br * (br + 1) / 2 > i)        br--;
        bc = i - br * (br + 1) / 2;
        m0 = br * TM; n0 = bc * TN;
        cbeg = 0; cend = DM / BK;
    } else if (MODE == 4) {
        // segment decode: segments per row i = ceil((i+1)/2); S(i)=floor((i+1)^2/4)
        const int idx = (int)blockIdx.x;
        const int q = idx >> 3;
        int i = (int)(2.0f * sqrtf((float)q));
        if (i > 31) i = 31;
        if (i < 0)  i = 0;
        while (i < 31 && ((i + 2) * (i + 2)) / 4 <= q) i++;
        while (i > 0  && ((i + 1) * (i + 1)) / 4 > q)  i--;
        const int u   = idx - 8 * (((i + 1) * (i + 1)) / 4);
        const int seg = u >> 3;
        const int j   = u & 7;
        m0 = i * TM; n0 = j * TN;
        cbeg = seg * SEGCH;
        const int nch_tot = 2 * (i + 1);          // chunks of 64
        cend = (cbeg + SEGCH < nch_tot) ? (cbeg + SEGCH) : nch_tot;
    } else {
        m0 = blockIdx.y * TM; n0 = blockIdx.x * TN;
        cbeg = 0; cend = DM / BK;
    }

    const __half *Aa, *Bb;
    int lda, ldb;
    int z = 0;
    if (MODE == 0) {
        z = (int)blockIdx.z + zbase;
        Aa = g_Xh; lda = DM; ldb = DM;
        Bb = g_Wt + (size_t)z * DM * DM;
    } else if (MODE == 3) {
        Aa = g_Q; lda = DM; ldb = DM;
        Bb = g_K;
    } else {
        Aa = g_P; lda = SEQ; ldb = DM;
        Bb = g_V;   // [k][n], n contiguous
    }

    float acc[2][8][4];
#pragma unroll
    for (int mi = 0; mi < 2; mi++)
#pragma unroll
        for (int nf = 0; nf < 8; nf++)
#pragma unroll
            for (int q2 = 0; q2 < 4; q2++) acc[mi][nf][q2] = 0.0f;

    // ---- chunk loader (stage = c % NSTAGE); 64 k-elements per chunk
    auto load_chunk = [&](int c) {
        const int k0  = c * BK;
        const uint32_t base = sb + (uint32_t)(c % NSTAGE) * BUFB;
        // A: 128 rows x 64 fp16 (128B/row, 8 chunks of 16B)
        for (int u2 = tid; u2 < 1024; u2 += NTHREADS) {
            int row = u2 >> 3, ch = u2 & 7;
            size_t go = (size_t)(m0 + row) * lda + k0 + ch * 8;
            CP16(base + row * A_PITCH + ch * 16, Aa + go);
        }
        if (MODE == 4) {
            // B: 64 k-rows x 128 n, XOR-swizzled 16B chunks
            for (int u2 = tid; u2 < 1024; u2 += NTHREADS) {
                int k = u2 >> 4, ch = u2 & 15;
                size_t go = (size_t)(k0 + k) * ldb + n0 + ch * 8;
                CP16(base + B_OFF + k * 256 + ((ch ^ (k & 7)) << 4), Bb + go);
            }
        } else {
            // B: 128 n-rows x 64 k (K-major, 144B pitch)
            for (int u2 = tid; u2 < 1024; u2 += NTHREADS) {
                int row = u2 >> 3, ch = u2 & 7;
                size_t gb = (size_t)(n0 + row) * ldb + k0 + ch * 8;
                CP16(base + B_OFF + row * A_PITCH + ch * 16, Bb + gb);
            }
        }
    };

    // 3-stage prologue
    load_chunk(cbeg);
    CP_COMMIT();
    if (cbeg + 1 < cend) { load_chunk(cbeg + 1); CP_COMMIT(); }

    for (int c = cbeg; c < cend; c++) {
        if (c + 2 < cend) { load_chunk(c + 2); CP_COMMIT(); CP_WAIT(2); }
        else if (c + 1 < cend) { CP_WAIT(1); }
        else { CP_WAIT(0); }
        __syncthreads();

        const uint32_t base = sb + (uint32_t)(c % NSTAGE) * BUFB;
#pragma unroll
        for (int ks = 0; ks < 4; ks++) {
            uint32_t ah[2][4];
#pragma unroll
            for (int mi = 0; mi < 2; mi++) {
                uint32_t aaddr = base
                    + (wr * 32 + mi * 16 + (lane & 15)) * A_PITCH
                    + (ks * 2 + (lane >> 4)) * 16;
                LDSM_X4(ah[mi], aaddr);
            }
            // B fragments: two n-tiles per ldmatrix.x4
#pragma unroll
            for (int nfp = 0; nfp < 4; nfp++) {
                uint32_t bh[4];
                if (MODE == 4) {
                    int klo    = ks * 16 + (lane & 15);
                    int cchunk = wc * 8 + nfp * 2 + ((lane >> 4) & 1);
                    uint32_t baddr = base + B_OFF + klo * 256
                        + ((cchunk ^ (klo & 7)) << 4);
                    LDSM_X4T(bh, baddr);
                } else {
                    uint32_t baddr = base + B_OFF
                        + (wc * 64 + nfp * 16 + (lane & 7) + ((lane >> 4) & 1) * 8) * A_PITCH
                        + ks * 32 + ((lane >> 3) & 1) * 16;
                    LDSM_X4(bh, baddr);
                }
#pragma unroll
                for (int mi = 0; mi < 2; mi++) {
                    MMA_F16(acc[mi][nfp * 2],     ah[mi], bh[0], bh[1]);
                    MMA_F16(acc[mi][nfp * 2 + 1], ah[mi], bh[2], bh[3]);
                }
            }
        }
        __syncthreads();
    }

    // ---- epilogue
    const int rb = m0 + wr * 32 + (lane >> 2);
    const int cb = n0 + wc * 64 + 2 * (lane & 3);

#pragma unroll
    for (int mi = 0; mi < 2; mi++) {
#pragma unroll
        for (int nf = 0; nf < 8; nf++) {
            int r0 = rb + mi * 16;
            int cc = cb + nf * 8;
            float v00 = acc[mi][nf][0], v01 = acc[mi][nf][1];
            float v10 = acc[mi][nf][2], v11 = acc[mi][nf][3];
            if (MODE == 0) {
                __half* Oq = (z == 0) ? g_Q : (z == 1) ? g_K : g_V;
                if (z == 0) {   // fold 1/sqrt(d) = 2^-5 into Q (exact)
                    v00 *= 0.03125f; v01 *= 0.03125f; v10 *= 0.03125f; v11 *= 0.03125f;
                }
                *(uint32_t*)(Oq + (size_t)r0 * DM + cc)       = packH2(v00, v01);
                *(uint32_t*)(Oq + (size_t)(r0 + 8) * DM + cc) = packH2(v10, v11);
            } else if (MODE == 3) {
                if (br == bc) {
                    float* s0 = g_S + (size_t)r0 * SEQ + cc;
                    s0[0] = (cc + 0 <= r0) ? v00 : -INFINITY;
                    s0[1] = (cc + 1 <= r0) ? v01 : -INFINITY;
                    float* s1 = g_S + (size_t)(r0 + 8) * SEQ + cc;
                    s1[0] = (cc + 0 <= r0 + 8) ? v10 : -INFINITY;
                    s1[1] = (cc + 1 <= r0 + 8) ? v11 : -INFINITY;
                } else {
                    *(float2*)(g_S + (size_t)r0 * SEQ + cc)       = make_float2(v00, v01);
                    *(float2*)(g_S + (size_t)(r0 + 8) * SEQ + cc) = make_float2(v10, v11);
                }
            } else {
                float* p0 = Oext + (size_t)r0 * DM + cc;
                float* p1 = Oext + (size_t)(r0 + 8) * DM + cc;
                atomicAdd(p0,     v00);
                atomicAdd(p0 + 1, v01);
                atomicAdd(p1,     v10);
                atomicAdd(p1 + 1, v11);
            }
        }
    }
}

// ---------------------------------------------------------------------------
// Row softmax over g_S; emits P fp16. Row r covers [0, roundup128(r+1)).
// Vectorized: float4 loads, uint2 fp16 stores.
// ---------------------------------------------------------------------------
__global__ __launch_bounds__(256) void softmax_kernel()
{
    const int r   = (int)blockIdx.x;
    const int L   = (((r >> 7) + 1) << 7);       // multiple of 128
    const float* row = g_S + (size_t)r * SEQ;
    const int tid = threadIdx.x;
    __shared__ float red[256];

    float4 v[4];
    int   cnt = 0;
    float mx  = -INFINITY;
    for (int c = tid * 4; c < L; c += 1024) {
        float4 t = *(const float4*)(row + c);
        v[cnt++] = t;
        mx = fmaxf(mx, fmaxf(fmaxf(t.x, t.y), fmaxf(t.z, t.w)));
    }
    red[tid] = mx;
    __syncthreads();
#pragma unroll
    for (int s = 128; s > 0; s >>= 1) {
        if (tid < s) red[tid] = fmaxf(red[tid], red[tid + s]);
        __syncthreads();
    }
    mx = red[0];
    __syncthreads();

    float sum = 0.0f;
    for (int j = 0; j < cnt; j++) {
        v[j].x = __expf(v[j].x - mx);
        v[j].y = __expf(v[j].y - mx);
        v[j].z = __expf(v[j].z - mx);
        v[j].w = __expf(v[j].w - mx);
        sum += (v[j].x + v[j].y) + (v[j].z + v[j].w);
    }
    red[tid] = sum;
    __syncthreads();
#pragma unroll
    for (int s = 128; s > 0; s >>= 1) {
        if (tid < s) red[tid] += red[tid + s];
        __syncthreads();
    }
    const float rinv = 1.0f / red[0];

    cnt = 0;
    for (int c = tid * 4; c < L; c += 1024) {
        float4 t = v[cnt++];
        *(uint2*)(g_P + (size_t)r * SEQ + c) =
            make_uint2(packH2(t.x * rinv, t.y * rinv), packH2(t.z * rinv, t.w * rinv));
    }
}

// ---------------------------------------------------------------------------
extern "C" void kernel_launch(void* const* d_in, const int* in_sizes, int n_in,
                              void* d_out, int out_size)
{
    const float* x  = (const float*)d_in[0];
    const float* Wq = (const float*)d_in[1];
    const float* Wk = (const float*)d_in[2];
    const float* Wv = (const float*)d_in[3];
    float* out = (float*)d_out;
    (void)in_sizes; (void)n_in;

    cudaFuncSetAttribute(hgemm<0>, cudaFuncAttributeMaxDynamicSharedMemorySize, SMEM_BYTES);
    cudaFuncSetAttribute(hgemm<3>, cudaFuncAttributeMaxDynamicSharedMemorySize, SMEM_BYTES);
    cudaFuncSetAttribute(hgemm<4>, cudaFuncAttributeMaxDynamicSharedMemorySize, SMEM_BYTES);

    // side stream + fork/join events
    cudaStream_t s2;
    cudaStreamCreate(&s2);
    cudaEvent_t eFork, eJoin;
    cudaEventCreateWithFlags(&eFork, cudaEventDisableTiming);
    cudaEventCreateWithFlags(&eJoin, cudaEventDisableTiming);

    // 0) operand prep (main stream)
    xhalf_kernel<<<SEQ * DM / (256 * 4), 256>>>(x);
    wtrans_kernel<<<dim3(DM / 32, DM / 32, 3), dim3(32, 8)>>>(Wq, Wk, Wv);

    // fork: V projection + output zeroing on side stream
    cudaEventRecord(eFork, 0);
    cudaStreamWaitEvent(s2, eFork, 0);
    cudaMemsetAsync(out, 0, (size_t)out_size * sizeof(float), s2);
    hgemm<0><<<dim3(DM / TN, SEQ / TM, 1), NTHREADS, SMEM_BYTES, s2>>>(nullptr, 2);  // V
    cudaEventRecord(eJoin, s2);

    // 1) Q,K projections (main stream)
    hgemm<0><<<dim3(DM / TN, SEQ / TM, 2), NTHREADS, SMEM_BYTES>>>(nullptr, 0);

    // 2) causal scores (lower-triangular blocks only, 1-pass fp16)
    const int nTri = (SEQ / TM) * (SEQ / TM + 1) / 2;   // 528
    hgemm<3><<<nTri, NTHREADS, SMEM_BYTES>>>(nullptr, 0);

    // 3) softmax -> P fp16
    softmax_kernel<<<SEQ, 256>>>();

    // join: PV needs V and the zeroed output
    cudaStreamWaitEvent(0, eJoin, 0);

    // 4) O = P @ V, split-K segments (2176 CTAs, 1-pass fp16)
    const int nSeg = 8 * ((33 * 33) / 4);   // 2176
    hgemm<4><<<nSeg, NTHREADS, SMEM_BYTES>>>(out, 0);
}

// round 16
// speedup vs baseline: 3.1867x; 1.0378x over previous
#include <cuda_runtime.h>
#include <cuda_bf16.h>
#include <cuda_fp16.h>
#include <math.h>
#include <stdint.h>

#define SEQ 4096
#define DM  1024
#define TM  128
#define TN  128
#define BK  64

#define NTHREADS 256

// PV split-K: 4 chunks (= 256 k-elements) per segment
#define SEGCH 4

// smem per stage: A[128 x 144B]  B[128 x 144B | 64 x 256B]
#define A_PITCH  144       // 128B data + 16B pad -> conflict-free ldmatrix
#define B_OFF    18432
#define BUFB     36864
#define NSTAGE   3
#define SMEM_BYTES (NSTAGE * BUFB)   // 110592 per CTA; x2 CTAs = 221 KB/SM

// ---------------- scratch (device globals; allocation-free) ----------------
__device__ __half  g_Xh [SEQ * DM];                 // X single fp16
__device__ __half  g_Q  [SEQ * DM];                 // Q single fp16 (pre-scaled by 1/32)
__device__ __half  g_K  [SEQ * DM];                 // K single fp16
__device__ __half  g_V  [SEQ * DM];                 // V single fp16
__device__ __half  g_Wt [3 * DM * DM];              // W^T [n][k] single fp16
__device__ __half  g_P  [(size_t)SEQ * SEQ];        // softmax out fp16
__device__ __half  g_S  [(size_t)SEQ * SEQ];        // scores fp16 (masked with -inf)

// ---------------- PTX helpers (baseline PTX only) ----------------
__device__ __forceinline__ uint32_t smem_u32(const void* p) {
    uint32_t a;
    asm("{ .reg .u64 t; cvta.to.shared.u64 t, %1; cvt.u32.u64 %0, t; }" : "=r"(a) : "l"(p));
    return a;
}

#define CP16(dst, src) \
    asm volatile("cp.async.cg.shared.global [%0], [%1], 16;" :: "r"(dst), "l"(src) : "memory")
#define CP_COMMIT() asm volatile("cp.async.commit_group;" ::: "memory")
#define CP_WAIT(n)  asm volatile("cp.async.wait_group %0;" :: "n"(n) : "memory")

#define LDSM_X4(r, addr) \
    asm volatile("ldmatrix.sync.aligned.m8n8.x4.shared.b16 {%0,%1,%2,%3}, [%4];" \
        : "=r"((r)[0]), "=r"((r)[1]), "=r"((r)[2]), "=r"((r)[3]) : "r"(addr))
#define LDSM_X4T(r, addr) \
    asm volatile("ldmatrix.sync.aligned.m8n8.x4.trans.shared.b16 {%0,%1,%2,%3}, [%4];" \
        : "=r"((r)[0]), "=r"((r)[1]), "=r"((r)[2]), "=r"((r)[3]) : "r"(addr))

#define MMA_F16(d, a, b0, b1) \
    asm volatile("mma.sync.aligned.m16n8k16.row.col.f32.f16.f16.f32 " \
        "{%0,%1,%2,%3}, {%4,%5,%6,%7}, {%8,%9}, {%0,%1,%2,%3};" \
        : "+f"((d)[0]), "+f"((d)[1]), "+f"((d)[2]), "+f"((d)[3]) \
        : "r"((a)[0]), "r"((a)[1]), "r"((a)[2]), "r"((a)[3]), "r"(b0), "r"(b1))

// ---------------- fp16 pack helper ----------------
__device__ __forceinline__ uint32_t packH2(float x, float y) {
    __half2 h;
    h.x = __float2half_rn(x);
    h.y = __float2half_rn(y);
    return *reinterpret_cast<uint32_t*>(&h);
}

// ---------------------------------------------------------------------------
// X -> fp16 single
// ---------------------------------------------------------------------------
__global__ __launch_bounds__(256) void xhalf_kernel(const float* __restrict__ x)
{
    int i = (blockIdx.x * 256 + threadIdx.x) * 4;
    float4 v = *(const float4*)(x + i);
    *(uint2*)(g_Xh + i) = make_uint2(packH2(v.x, v.y), packH2(v.z, v.w));
}

// ---------------------------------------------------------------------------
// W transpose: W [k][n] fp32 -> Wt [n][k] single fp16
// ---------------------------------------------------------------------------
__global__ __launch_bounds__(256) void wtrans_kernel(
    const float* __restrict__ Wq, const float* __restrict__ Wk, const float* __restrict__ Wv)
{
    __shared__ float t[32][33];
    const float* W = (blockIdx.z == 0) ? Wq : (blockIdx.z == 1) ? Wk : Wv;
    const size_t zoff = (size_t)blockIdx.z * DM * DM;
    const int n0 = blockIdx.x * 32, k0 = blockIdx.y * 32;
    const int tx = threadIdx.x, ty = threadIdx.y;  // (32, 8)

#pragma unroll
    for (int j = 0; j < 32; j += 8)
        t[ty + j][tx] = W[(size_t)(k0 + ty + j) * DM + n0 + tx];
    __syncthreads();
#pragma unroll
    for (int j = 0; j < 32; j += 8) {
        float v = t[tx][ty + j];
        g_Wt[zoff + (size_t)(n0 + ty + j) * DM + k0 + tx] = __float2half_rn(v);
    }
}

// ---------------------------------------------------------------------------
// Unified 1-pass fp16 mma.sync GEMM. 128x128 CTA tile, 8 warps of 32x64,
// BK=64, cp.async 3-stage ring with single barrier per chunk, 2 CTAs/SM.
//  MODE 0: proj (z=blockIdx.z+zbase: 0=Q,1=K,2=V). A=Xh, B=Wt[z].
//          Q is written pre-scaled by 1/32.
//  MODE 3: scores. A=Q(pre-scaled), B=K. tri grid; g_S fp16 + causal -inf.
//  MODE 4: PV split-K. A=P, B=V [k][n] (trans ldmatrix). atomicAdd into Oext.
// ---------------------------------------------------------------------------
template<int MODE>
__global__ __launch_bounds__(NTHREADS, 2) void hgemm(float* __restrict__ Oext, int zbase)
{
    extern __shared__ char smem[];
    const uint32_t sb = smem_u32(smem);
    const int tid  = threadIdx.x;
    const int wid  = tid >> 5;
    const int lane = tid & 31;
    const int wr   = wid & 3;        // warp row (32 rows)
    const int wc   = wid >> 2;       // warp col (64 cols)

    int m0, n0, br = 0, bc = 0;
    int cbeg = 0, cend = 0;
    if (MODE == 3) {
        int i = (int)blockIdx.x;
        br = (int)((sqrtf(8.0f * (float)i + 1.0f) - 1.0f) * 0.5f);
        while ((br + 1) * (br + 2) / 2 <= i) br++;
        while (br * (br + 1) / 2 > i)        br--;
        bc = i - br * (br + 1) / 2;
        m0 = br * TM; n0 = bc * TN;
        cbeg = 0; cend = DM / BK;
    } else if (MODE == 4) {
        // segment decode: segments per row i = ceil((i+1)/2); S(i)=floor((i+1)^2/4)
        const int idx = (int)blockIdx.x;
        const int q = idx >> 3;
        int i = (int)(2.0f * sqrtf((float)q));
        if (i > 31) i = 31;
        if (i < 0)  i = 0;
        while (i < 31 && ((i + 2) * (i + 2)) / 4 <= q) i++;
        while (i > 0  && ((i + 1) * (i + 1)) / 4 > q)  i--;
        const int u   = idx - 8 * (((i + 1) * (i + 1)) / 4);
        const int seg = u >> 3;
        const int j   = u & 7;
        m0 = i * TM; n0 = j * TN;
        cbeg = seg * SEGCH;
        const int nch_tot = 2 * (i + 1);          // chunks of 64
        cend = (cbeg + SEGCH < nch_tot) ? (cbeg + SEGCH) : nch_tot;
    } else {
        m0 = blockIdx.y * TM; n0 = blockIdx.x * TN;
        cbeg = 0; cend = DM / BK;
    }

    const __half *Aa, *Bb;
    int lda, ldb;
    int z = 0;
    if (MODE == 0) {
        z = (int)blockIdx.z + zbase;
        Aa = g_Xh; lda = DM; ldb = DM;
        Bb = g_Wt + (size_t)z * DM * DM;
    } else if (MODE == 3) {
        Aa = g_Q; lda = DM; ldb = DM;
        Bb = g_K;
    } else {
        Aa = g_P; lda = SEQ; ldb = DM;
        Bb = g_V;   // [k][n], n contiguous
    }

    float acc[2][8][4];
#pragma unroll
    for (int mi = 0; mi < 2; mi++)
#pragma unroll
        for (int nf = 0; nf < 8; nf++)
#pragma unroll
            for (int q2 = 0; q2 < 4; q2++) acc[mi][nf][q2] = 0.0f;

    // ---- chunk loader (stage = c % NSTAGE); 64 k-elements per chunk
    auto load_chunk = [&](int c) {
        const int k0  = c * BK;
        const uint32_t base = sb + (uint32_t)(c % NSTAGE) * BUFB;
        // A: 128 rows x 64 fp16 (128B/row, 8 chunks of 16B)
        for (int u2 = tid; u2 < 1024; u2 += NTHREADS) {
            int row = u2 >> 3, ch = u2 & 7;
            size_t go = (size_t)(m0 + row) * lda + k0 + ch * 8;
            CP16(base + row * A_PITCH + ch * 16, Aa + go);
        }
        if (MODE == 4) {
            // B: 64 k-rows x 128 n, XOR-swizzled 16B chunks
            for (int u2 = tid; u2 < 1024; u2 += NTHREADS) {
                int k = u2 >> 4, ch = u2 & 15;
                size_t go = (size_t)(k0 + k) * ldb + n0 + ch * 8;
                CP16(base + B_OFF + k * 256 + ((ch ^ (k & 7)) << 4), Bb + go);
            }
        } else {
            // B: 128 n-rows x 64 k (K-major, 144B pitch)
            for (int u2 = tid; u2 < 1024; u2 += NTHREADS) {
                int row = u2 >> 3, ch = u2 & 7;
                size_t gb = (size_t)(n0 + row) * ldb + k0 + ch * 8;
                CP16(base + B_OFF + row * A_PITCH + ch * 16, Bb + gb);
            }
        }
    };

    // 3-stage prologue
    load_chunk(cbeg);
    CP_COMMIT();
    if (cbeg + 1 < cend) { load_chunk(cbeg + 1); CP_COMMIT(); }

    for (int c = cbeg; c < cend; c++) {
        // single barrier per chunk: after it, all warps are done reading
        // stage (c-1)%3 == stage (c+2)%3, so issuing load(c+2) is safe here.
        if (c + 1 < cend) { CP_WAIT(1); } else { CP_WAIT(0); }
        __syncthreads();
        if (c + 2 < cend) { load_chunk(c + 2); CP_COMMIT(); }

        const uint32_t base = sb + (uint32_t)(c % NSTAGE) * BUFB;
#pragma unroll
        for (int ks = 0; ks < 4; ks++) {
            uint32_t ah[2][4];
#pragma unroll
            for (int mi = 0; mi < 2; mi++) {
                uint32_t aaddr = base
                    + (wr * 32 + mi * 16 + (lane & 15)) * A_PITCH
                    + (ks * 2 + (lane >> 4)) * 16;
                LDSM_X4(ah[mi], aaddr);
            }
            // B fragments: two n-tiles per ldmatrix.x4
#pragma unroll
            for (int nfp = 0; nfp < 4; nfp++) {
                uint32_t bh[4];
                if (MODE == 4) {
                    int klo    = ks * 16 + (lane & 15);
                    int cchunk = wc * 8 + nfp * 2 + ((lane >> 4) & 1);
                    uint32_t baddr = base + B_OFF + klo * 256
                        + ((cchunk ^ (klo & 7)) << 4);
                    LDSM_X4T(bh, baddr);
                } else {
                    uint32_t baddr = base + B_OFF
                        + (wc * 64 + nfp * 16 + (lane & 7) + ((lane >> 4) & 1) * 8) * A_PITCH
                        + ks * 32 + ((lane >> 3) & 1) * 16;
                    LDSM_X4(bh, baddr);
                }
#pragma unroll
                for (int mi = 0; mi < 2; mi++) {
                    MMA_F16(acc[mi][nfp * 2],     ah[mi], bh[0], bh[1]);
                    MMA_F16(acc[mi][nfp * 2 + 1], ah[mi], bh[2], bh[3]);
                }
            }
        }
        // no bottom barrier: the next iteration's top barrier provides it
    }

    // ---- epilogue
    const int rb = m0 + wr * 32 + (lane >> 2);
    const int cb = n0 + wc * 64 + 2 * (lane & 3);

#pragma unroll
    for (int mi = 0; mi < 2; mi++) {
#pragma unroll
        for (int nf = 0; nf < 8; nf++) {
            int r0 = rb + mi * 16;
            int cc = cb + nf * 8;
            float v00 = acc[mi][nf][0], v01 = acc[mi][nf][1];
            float v10 = acc[mi][nf][2], v11 = acc[mi][nf][3];
            if (MODE == 0) {
                __half* Oq = (z == 0) ? g_Q : (z == 1) ? g_K : g_V;
                if (z == 0) {   // fold 1/sqrt(d) = 2^-5 into Q (exact)
                    v00 *= 0.03125f; v01 *= 0.03125f; v10 *= 0.03125f; v11 *= 0.03125f;
                }
                *(uint32_t*)(Oq + (size_t)r0 * DM + cc)       = packH2(v00, v01);
                *(uint32_t*)(Oq + (size_t)(r0 + 8) * DM + cc) = packH2(v10, v11);
            } else if (MODE == 3) {
                if (br == bc) {
                    *(uint32_t*)(g_S + (size_t)r0 * SEQ + cc) =
                        packH2((cc + 0 <= r0) ? v00 : -INFINITY,
                               (cc + 1 <= r0) ? v01 : -INFINITY);
                    *(uint32_t*)(g_S + (size_t)(r0 + 8) * SEQ + cc) =
                        packH2((cc + 0 <= r0 + 8) ? v10 : -INFINITY,
                               (cc + 1 <= r0 + 8) ? v11 : -INFINITY);
                } else {
                    *(uint32_t*)(g_S + (size_t)r0 * SEQ + cc)       = packH2(v00, v01);
                    *(uint32_t*)(g_S + (size_t)(r0 + 8) * SEQ + cc) = packH2(v10, v11);
                }
            } else {
                float* p0 = Oext + (size_t)r0 * DM + cc;
                float* p1 = Oext + (size_t)(r0 + 8) * DM + cc;
                atomicAdd(p0,     v00);
                atomicAdd(p0 + 1, v01);
                atomicAdd(p1,     v10);
                atomicAdd(p1 + 1, v11);
            }
        }
    }
}

// ---------------------------------------------------------------------------
// Row softmax over g_S (fp16, -inf masked); emits P fp16.
// Row r covers [0, roundup128(r+1)). 8-half vector loads; statically
// unrolled register-resident values (max 16 floats/thread).
// ---------------------------------------------------------------------------
__global__ __launch_bounds__(256) void softmax_kernel()
{
    const int r   = (int)blockIdx.x;
    const int L   = (((r >> 7) + 1) << 7);       // multiple of 128, <= 4096
    const __half* row = g_S + (size_t)r * SEQ;
    const int tid = threadIdx.x;
    __shared__ float red[256];

    float f[16];
    float mx = -INFINITY;
#pragma unroll
    for (int t = 0; t < 2; t++) {
        int c = tid * 8 + t * 2048;
        if (c < L) {
            uint4 raw = *(const uint4*)(row + c);
            const __half2* h2 = reinterpret_cast<const __half2*>(&raw);
#pragma unroll
            for (int j = 0; j < 4; j++) {
                float2 p = __half22float2(h2[j]);
                f[t * 8 + j * 2]     = p.x;
                f[t * 8 + j * 2 + 1] = p.y;
                mx = fmaxf(mx, fmaxf(p.x, p.y));
            }
        }
    }
    red[tid] = mx;
    __syncthreads();
#pragma unroll
    for (int s = 128; s > 0; s >>= 1) {
        if (tid < s) red[tid] = fmaxf(red[tid], red[tid + s]);
        __syncthreads();
    }
    mx = red[0];
    __syncthreads();

    float sum = 0.0f;
#pragma unroll
    for (int t = 0; t < 2; t++) {
        int c = tid * 8 + t * 2048;
        if (c < L) {
#pragma unroll
            for (int j = 0; j < 8; j++) {
                f[t * 8 + j] = __expf(f[t * 8 + j] - mx);
                sum += f[t * 8 + j];
            }
        }
    }
    red[tid] = sum;
    __syncthreads();
#pragma unroll
    for (int s = 128; s > 0; s >>= 1) {
        if (tid < s) red[tid] += red[tid + s];
        __syncthreads();
    }
    const float rinv = 1.0f / red[0];

#pragma unroll
    for (int t = 0; t < 2; t++) {
        int c = tid * 8 + t * 2048;
        if (c < L) {
            uint4 o;
            o.x = packH2(f[t * 8 + 0] * rinv, f[t * 8 + 1] * rinv);
            o.y = packH2(f[t * 8 + 2] * rinv, f[t * 8 + 3] * rinv);
            o.z = packH2(f[t * 8 + 4] * rinv, f[t * 8 + 5] * rinv);
            o.w = packH2(f[t * 8 + 6] * rinv, f[t * 8 + 7] * rinv);
            *(uint4*)(g_P + (size_t)r * SEQ + c) = o;
        }
    }
}

// ---------------------------------------------------------------------------
extern "C" void kernel_launch(void* const* d_in, const int* in_sizes, int n_in,
                              void* d_out, int out_size)
{
    const float* x  = (const float*)d_in[0];
    const float* Wq = (const float*)d_in[1];
    const float* Wk = (const float*)d_in[2];
    const float* Wv = (const float*)d_in[3];
    float* out = (float*)d_out;
    (void)in_sizes; (void)n_in;

    cudaFuncSetAttribute(hgemm<0>, cudaFuncAttributeMaxDynamicSharedMemorySize, SMEM_BYTES);
    cudaFuncSetAttribute(hgemm<3>, cudaFuncAttributeMaxDynamicSharedMemorySize, SMEM_BYTES);
    cudaFuncSetAttribute(hgemm<4>, cudaFuncAttributeMaxDynamicSharedMemorySize, SMEM_BYTES);

    // side stream + fork/join events
    cudaStream_t s2;
    cudaStreamCreate(&s2);
    cudaEvent_t eFork, eJoin;
    cudaEventCreateWithFlags(&eFork, cudaEventDisableTiming);
    cudaEventCreateWithFlags(&eJoin, cudaEventDisableTiming);

    // 0) operand prep (main stream)
    xhalf_kernel<<<SEQ * DM / (256 * 4), 256>>>(x);
    wtrans_kernel<<<dim3(DM / 32, DM / 32, 3), dim3(32, 8)>>>(Wq, Wk, Wv);

    // fork: V projection + output zeroing on side stream
    cudaEventRecord(eFork, 0);
    cudaStreamWaitEvent(s2, eFork, 0);
    cudaMemsetAsync(out, 0, (size_t)out_size * sizeof(float), s2);
    hgemm<0><<<dim3(DM / TN, SEQ / TM, 1), NTHREADS, SMEM_BYTES, s2>>>(nullptr, 2);  // V
    cudaEventRecord(eJoin, s2);

    // 1) Q,K projections (main stream)
    hgemm<0><<<dim3(DM / TN, SEQ / TM, 2), NTHREADS, SMEM_BYTES>>>(nullptr, 0);

    // 2) causal scores (lower-triangular blocks only, 1-pass fp16, fp16 S out)
    const int nTri = (SEQ / TM) * (SEQ / TM + 1) / 2;   // 528
    hgemm<3><<<nTri, NTHREADS, SMEM_BYTES>>>(nullptr, 0);

    // 3) softmax -> P fp16
    softmax_kernel<<<SEQ, 256>>>();

    // join: PV needs V and the zeroed output
    cudaStreamWaitEvent(0, eJoin, 0);

    // 4) O = P @ V, split-K segments (2176 CTAs, 1-pass fp16)
    const int nSeg = 8 * ((33 * 33) / 4);   // 2176
    hgemm<4><<<nSeg, NTHREADS, SMEM_BYTES>>>(out, 0);
}